// round 2
// baseline (speedup 1.0000x reference)
#include <cuda_runtime.h>
#include <math.h>
#include <float.h>

#define LAYERS 6
#define DIM    16
#define NH     8
#define DHD    4
#define NBATCH 16
#define BOTD   26
#define FFDIM  64
#define NTOK   50625
#define CHUNKS 64
#define TPB    256
#define LN_EPS 1e-5f

// ---------------- static scratch (no allocations allowed) ----------------
__device__ __align__(16) float  g_x[(size_t)NBATCH * NTOK * DIM];   // residual stream, fp32
__device__ __align__(16) float4 g_rot[NTOK];                        // c0,s0,c1,s1
__device__ float g_part[NBATCH * NH * CHUNKS * 6];                  // online-softmax block partials
__device__ float g_gq[NBATCH * NH * DHD];                           // global_q
__device__ float g_gk[NBATCH * NH * DHD];                           // global_k

// ---------------- online softmax state ----------------
struct OS { float m, s, w0, w1, w2, w3; };

__device__ __forceinline__ void os_init(OS &o) {
    o.m = -INFINITY; o.s = 0.f; o.w0 = o.w1 = o.w2 = o.w3 = 0.f;
}

__device__ __forceinline__ void os_update(OS &o, float l, float a0, float a1, float a2, float a3) {
    if (l > o.m) {
        float p = __expf(o.m - l);          // exp(-inf)=0 on first update
        o.s  = o.s * p + 1.f;
        o.w0 = o.w0 * p + a0; o.w1 = o.w1 * p + a1;
        o.w2 = o.w2 * p + a2; o.w3 = o.w3 * p + a3;
        o.m = l;
    } else {
        float p = __expf(l - o.m);
        o.s += p;
        o.w0 += p * a0; o.w1 += p * a1; o.w2 += p * a2; o.w3 += p * a3;
    }
}

__device__ __forceinline__ void os_merge(OS &a, const OS &b) {
    if (b.m == -INFINITY) return;           // empty partial
    if (b.m > a.m) {
        float p = __expf(a.m - b.m);
        a.s  = a.s * p + b.s;
        a.w0 = a.w0 * p + b.w0; a.w1 = a.w1 * p + b.w1;
        a.w2 = a.w2 * p + b.w2; a.w3 = a.w3 * p + b.w3;
        a.m = b.m;
    } else {
        float p = __expf(b.m - a.m);
        a.s += b.s * p;
        a.w0 += b.w0 * p; a.w1 += b.w1 * p;
        a.w2 += b.w2 * p; a.w3 += b.w3 * p;
    }
}

// warp-shuffle + smem reduction of per-thread states -> per-block partial
__device__ __forceinline__ void block_reduce_store(OS st[NH], int b, int chunk) {
    const unsigned FULL = 0xffffffffu;
    #pragma unroll
    for (int off = 16; off; off >>= 1) {
        #pragma unroll
        for (int h = 0; h < NH; h++) {
            OS o;
            o.m  = __shfl_xor_sync(FULL, st[h].m,  off);
            o.s  = __shfl_xor_sync(FULL, st[h].s,  off);
            o.w0 = __shfl_xor_sync(FULL, st[h].w0, off);
            o.w1 = __shfl_xor_sync(FULL, st[h].w1, off);
            o.w2 = __shfl_xor_sync(FULL, st[h].w2, off);
            o.w3 = __shfl_xor_sync(FULL, st[h].w3, off);
            os_merge(st[h], o);
        }
    }
    __shared__ OS sred[TPB / 32][NH];
    int wid = threadIdx.x >> 5, lane = threadIdx.x & 31;
    if (lane == 0) {
        #pragma unroll
        for (int h = 0; h < NH; h++) sred[wid][h] = st[h];
    }
    __syncthreads();
    if (threadIdx.x < NH) {
        int h = threadIdx.x;
        OS acc = sred[0][h];
        #pragma unroll
        for (int w = 1; w < TPB / 32; w++) os_merge(acc, sred[w][h]);
        float *dst = &g_part[((b * NH + h) * CHUNKS + chunk) * 6];
        dst[0] = acc.m; dst[1] = acc.s;
        dst[2] = acc.w0; dst[3] = acc.w1; dst[4] = acc.w2; dst[5] = acc.w3;
    }
}

// ---------------- small helpers ----------------
__device__ __forceinline__ void load16(const float *p, float x[16]) {
    const float4 *p4 = (const float4 *)p;
    #pragma unroll
    for (int i = 0; i < 4; i++) {
        float4 v = p4[i];
        x[i * 4] = v.x; x[i * 4 + 1] = v.y; x[i * 4 + 2] = v.z; x[i * 4 + 3] = v.w;
    }
}
__device__ __forceinline__ void store16(float *p, const float x[16]) {
    float4 *p4 = (float4 *)p;
    #pragma unroll
    for (int i = 0; i < 4; i++)
        p4[i] = make_float4(x[i * 4], x[i * 4 + 1], x[i * 4 + 2], x[i * 4 + 3]);
}

__device__ __forceinline__ void ln16(const float x[16], const float *g, const float *b, float y[16]) {
    float m = 0.f;
    #pragma unroll
    for (int d = 0; d < 16; d++) m += x[d];
    m *= 0.0625f;
    float v = 0.f;
    #pragma unroll
    for (int d = 0; d < 16; d++) { float t = x[d] - m; v = fmaf(t, t, v); }
    v *= 0.0625f;
    float inv = rsqrtf(v + LN_EPS);
    #pragma unroll
    for (int d = 0; d < 16; d++) y[d] = (x[d] - m) * inv * g[d] + b[d];
}

// y[16] . W[16x32] four columns starting at `col` (col % 4 == 0)
__device__ __forceinline__ void dot16x4(const float y[16], const float *W, int col,
                                        float &o0, float &o1, float &o2, float &o3) {
    o0 = o1 = o2 = o3 = 0.f;
    #pragma unroll
    for (int d = 0; d < 16; d++) {
        float4 w = *(const float4 *)(W + d * 32 + col);
        float yd = y[d];
        o0 = fmaf(yd, w.x, o0); o1 = fmaf(yd, w.y, o1);
        o2 = fmaf(yd, w.z, o2); o3 = fmaf(yd, w.w, o3);
    }
}

// pass-A work for one token (q logits + rotary aggr + online softmax)
__device__ __forceinline__ void passA_token(const float x[16], float4 rt,
                                            const float *lg, const float *lb,
                                            const float *Wq, const float *wql, OS st[NH]) {
    float y[16];
    ln16(x, lg, lb, y);
    #pragma unroll
    for (int h = 0; h < NH; h++) {
        float q0, q1, q2, q3;
        dot16x4(y, Wq, h * 4, q0, q1, q2, q3);
        float l = (q0 * wql[0] + q1 * wql[1] + q2 * wql[2] + q3 * wql[3]) * 0.5f;
        float a0 = q0 * rt.x - q1 * rt.y;
        float a1 = q1 * rt.x + q0 * rt.y;
        float a2 = q2 * rt.z - q3 * rt.w;
        float a3 = q3 * rt.z + q2 * rt.w;
        os_update(st[h], l, a0, a1, a2, a3);
    }
}

// ---------------- kernels ----------------
__global__ void k_rot() {
    int n = blockIdx.x * blockDim.x + threadIdx.x;
    if (n >= NTOK) return;
    float t = (float)n;
    float f0 = t * (float)M_PI;          // fp32-rounded products, matching jnp
    float f1 = t * (float)(5.0 * M_PI);
    float s0, c0, s1, c1;
    sincosf(f0, &s0, &c0);
    sincosf(f1, &s1, &c1);
    g_rot[n] = make_float4(c0, s0, c1, s1);
}

// embedding + fused pass-A of layer 0
__global__ void __launch_bounds__(TPB) k_embed(
    const float *__restrict__ corr, const float *__restrict__ Wemb, const float *__restrict__ bemb,
    const float *__restrict__ ln1g, const float *__restrict__ ln1b,
    const float *__restrict__ Wqkv, const float *__restrict__ wqlog) {
    __shared__ __align__(16) float sWemb[BOTD * DIM];
    __shared__ float sbemb[DIM], sln1g[DIM], sln1b[DIM], swql[4];
    __shared__ __align__(16) float sWq[DIM * 32];
    int tid = threadIdx.x;
    for (int i = tid; i < BOTD * DIM; i += TPB) sWemb[i] = Wemb[i];
    for (int i = tid; i < DIM; i += TPB) { sbemb[i] = bemb[i]; sln1g[i] = ln1g[i]; sln1b[i] = ln1b[i]; }
    for (int i = tid; i < DIM * 32; i += TPB) { int d = i >> 5, c = i & 31; sWq[i] = Wqkv[d * 96 + c]; }
    if (tid < 4) swql[tid] = wqlog[tid];
    __syncthreads();

    int b = blockIdx.y;
    const float *cb = corr + (size_t)b * BOTD * NTOK;
    OS st[NH];
    #pragma unroll
    for (int h = 0; h < NH; h++) os_init(st[h]);

    for (int n = blockIdx.x * TPB + tid; n < NTOK; n += CHUNKS * TPB) {
        float x[16];
        #pragma unroll
        for (int d = 0; d < 16; d++) x[d] = sbemb[d];
        #pragma unroll
        for (int c = 0; c < BOTD; c++) {
            float cv = fmaxf(cb[c * NTOK + n], 0.f);
            #pragma unroll
            for (int d4 = 0; d4 < 4; d4++) {
                float4 w = *(const float4 *)(sWemb + c * 16 + d4 * 4);
                x[d4 * 4 + 0] = fmaf(cv, w.x, x[d4 * 4 + 0]);
                x[d4 * 4 + 1] = fmaf(cv, w.y, x[d4 * 4 + 1]);
                x[d4 * 4 + 2] = fmaf(cv, w.z, x[d4 * 4 + 2]);
                x[d4 * 4 + 3] = fmaf(cv, w.w, x[d4 * 4 + 3]);
            }
        }
        store16(g_x + ((size_t)b * NTOK + n) * DIM, x);
        passA_token(x, g_rot[n], sln1g, sln1b, sWq, swql, st);
    }
    block_reduce_store(st, b, blockIdx.x);
}

// merge block partials -> global_q (which=0) or global_k (which=1)
__global__ void k_reduce(int which) {
    int bh = threadIdx.x;
    if (bh >= NBATCH * NH) return;
    const float *base = &g_part[bh * CHUNKS * 6];
    OS acc; os_init(acc);
    for (int c = 0; c < CHUNKS; c++) {
        const float *p = base + c * 6;
        OS o; o.m = p[0]; o.s = p[1]; o.w0 = p[2]; o.w1 = p[3]; o.w2 = p[4]; o.w3 = p[5];
        os_merge(acc, o);
    }
    float inv = 1.f / acc.s;
    float *glob = which ? g_gk : g_gq;
    glob[bh * 4 + 0] = acc.w0 * inv; glob[bh * 4 + 1] = acc.w1 * inv;
    glob[bh * 4 + 2] = acc.w2 * inv; glob[bh * 4 + 3] = acc.w3 * inv;
}

// pass-B: k -> k2 logits -> online softmax of k_aggr
__global__ void __launch_bounds__(TPB) k_passB(
    const float *__restrict__ ln1g_all, const float *__restrict__ ln1b_all,
    const float *__restrict__ Wqkv, const float *__restrict__ wklog_all, int layer) {
    __shared__ float sln1g[16], sln1b[16], swkl[2], sgq[NH * 4];
    __shared__ __align__(16) float sWk[DIM * 32];
    int tid = threadIdx.x, b = blockIdx.y;
    for (int i = tid; i < 16; i += TPB) { sln1g[i] = ln1g_all[layer * 16 + i]; sln1b[i] = ln1b_all[layer * 16 + i]; }
    for (int i = tid; i < 512; i += TPB) { int d = i >> 5, c = i & 31; sWk[i] = Wqkv[(layer * 16 + d) * 96 + 32 + c]; }
    if (tid < 2) swkl[tid] = wklog_all[layer * 2 + tid];
    for (int i = tid; i < 32; i += TPB) sgq[i] = g_gq[b * 32 + i];
    __syncthreads();

    OS st[NH];
    #pragma unroll
    for (int h = 0; h < NH; h++) os_init(st[h]);

    for (int n = blockIdx.x * TPB + tid; n < NTOK; n += CHUNKS * TPB) {
        float x[16], y[16];
        load16(g_x + ((size_t)b * NTOK + n) * DIM, x);
        ln16(x, sln1g, sln1b, y);
        float4 rt = g_rot[n];
        #pragma unroll
        for (int h = 0; h < NH; h++) {
            float k0, k1, k2v, k3;
            dot16x4(y, sWk, h * 4, k0, k1, k2v, k3);
            float ka = k0 * sgq[h * 4 + 0] + k1 * sgq[h * 4 + 1];
            float kb = k2v * sgq[h * 4 + 2] + k3 * sgq[h * 4 + 3];
            float l  = (ka * swkl[0] + kb * swkl[1]) * 0.5f;
            float a0 = k0 * rt.x - k1 * rt.y;
            float a1 = k1 * rt.x + k0 * rt.y;
            float a2 = k2v * rt.z - k3 * rt.w;
            float a3 = k3 * rt.z + k2v * rt.w;
            os_update(st[h], l, a0, a1, a2, a3);
        }
    }
    block_reduce_store(st, b, blockIdx.x);
}

// pass-C: v->u->r->W_o->residual->LN2->FF->residual, fused with next layer pass-A
__global__ void __launch_bounds__(TPB) k_passC(
    const float *__restrict__ ln1g_all, const float *__restrict__ ln1b_all,
    const float *__restrict__ Wqkv,
    const float *__restrict__ Wr_all, const float *__restrict__ br_all,
    const float *__restrict__ Wo_all, const float *__restrict__ bo_all,
    const float *__restrict__ ln2g_all, const float *__restrict__ ln2b_all,
    const float *__restrict__ Wff1_all, const float *__restrict__ bff1_all,
    const float *__restrict__ Wff2_all, const float *__restrict__ bff2_all,
    const float *__restrict__ wqlog_all,
    const float *__restrict__ Wout, const float *__restrict__ bout,
    float *__restrict__ out, int layer, int last) {
    __shared__ float sln1g[16], sln1b[16], sWr[8], sbr[4], sbo[16];
    __shared__ float sln2g[16], sln2b[16], sbff1[64], sbff2[16], sgk[32];
    __shared__ float sln1gN[16], sln1bN[16], swqlN[4], sWout[16], sbout;
    __shared__ __align__(16) float sWq[512], sWv[512], sWo[512];
    __shared__ __align__(16) float sWff1[1024], sWff2[1024], sWqN[512];
    int tid = threadIdx.x, b = blockIdx.y;

    for (int i = tid; i < 512; i += TPB) {
        int d = i >> 5, c = i & 31;
        sWq[i] = Wqkv[(layer * 16 + d) * 96 + c];
        sWv[i] = Wqkv[(layer * 16 + d) * 96 + 64 + c];
        sWo[i] = Wo_all[layer * 512 + i];
    }
    for (int i = tid; i < 1024; i += TPB) {
        sWff1[i] = Wff1_all[layer * 1024 + i];
        sWff2[i] = Wff2_all[layer * 1024 + i];
    }
    for (int i = tid; i < 64; i += TPB) sbff1[i] = bff1_all[layer * 64 + i];
    for (int i = tid; i < 16; i += TPB) {
        sln1g[i] = ln1g_all[layer * 16 + i]; sln1b[i] = ln1b_all[layer * 16 + i];
        sbo[i]   = bo_all[layer * 16 + i];
        sln2g[i] = ln2g_all[layer * 16 + i]; sln2b[i] = ln2b_all[layer * 16 + i];
        sbff2[i] = bff2_all[layer * 16 + i];
    }
    if (tid < 8) sWr[tid] = Wr_all[layer * 8 + tid];
    if (tid < 4) sbr[tid] = br_all[layer * 4 + tid];
    for (int i = tid; i < 32; i += TPB) sgk[i] = g_gk[b * 32 + i];
    if (!last) {
        int nl = layer + 1;
        for (int i = tid; i < 512; i += TPB) { int d = i >> 5, c = i & 31; sWqN[i] = Wqkv[(nl * 16 + d) * 96 + c]; }
        for (int i = tid; i < 16; i += TPB) { sln1gN[i] = ln1g_all[nl * 16 + i]; sln1bN[i] = ln1b_all[nl * 16 + i]; }
        if (tid < 4) swqlN[tid] = wqlog_all[nl * 4 + tid];
    } else {
        for (int i = tid; i < 16; i += TPB) sWout[i] = Wout[i];
        if (tid == 0) sbout = bout[0];
    }
    __syncthreads();

    OS st[NH];
    #pragma unroll
    for (int h = 0; h < NH; h++) os_init(st[h]);

    for (int n = blockIdx.x * TPB + tid; n < NTOK; n += CHUNKS * TPB) {
        float x[16], y[16];
        float *xptr = g_x + ((size_t)b * NTOK + n) * DIM;
        load16(xptr, x);
        ln16(x, sln1g, sln1b, y);

        // heads: q, v, u, r  (r = u@W_r + b_r + q)
        float r[32];
        #pragma unroll
        for (int h = 0; h < NH; h++) {
            float q0, q1, q2, q3, v0, v1, v2, v3;
            dot16x4(y, sWq, h * 4, q0, q1, q2, q3);
            dot16x4(y, sWv, h * 4, v0, v1, v2, v3);
            float u0 = v0 * sgk[h * 4 + 0] + v1 * sgk[h * 4 + 1];
            float u1 = v2 * sgk[h * 4 + 2] + v3 * sgk[h * 4 + 3];
            r[h * 4 + 0] = u0 * sWr[0] + u1 * sWr[4] + sbr[0] + q0;
            r[h * 4 + 1] = u0 * sWr[1] + u1 * sWr[5] + sbr[1] + q1;
            r[h * 4 + 2] = u0 * sWr[2] + u1 * sWr[6] + sbr[2] + q2;
            r[h * 4 + 3] = u0 * sWr[3] + u1 * sWr[7] + sbr[3] + q3;
        }
        // output projection + residual
        float o[16];
        #pragma unroll
        for (int d = 0; d < 16; d++) o[d] = sbo[d];
        #pragma unroll
        for (int c = 0; c < 32; c++) {
            float rc = r[c];
            #pragma unroll
            for (int d4 = 0; d4 < 4; d4++) {
                float4 w = *(const float4 *)(sWo + c * 16 + d4 * 4);
                o[d4 * 4 + 0] = fmaf(rc, w.x, o[d4 * 4 + 0]);
                o[d4 * 4 + 1] = fmaf(rc, w.y, o[d4 * 4 + 1]);
                o[d4 * 4 + 2] = fmaf(rc, w.z, o[d4 * 4 + 2]);
                o[d4 * 4 + 3] = fmaf(rc, w.w, o[d4 * 4 + 3]);
            }
        }
        #pragma unroll
        for (int d = 0; d < 16; d++) x[d] += o[d];

        // FF block
        ln16(x, sln2g, sln2b, y);
        float acc[16];
        #pragma unroll
        for (int d = 0; d < 16; d++) acc[d] = 0.f;
        #pragma unroll
        for (int j4 = 0; j4 < 16; j4++) {
            float t0 = sbff1[j4 * 4 + 0], t1 = sbff1[j4 * 4 + 1];
            float t2 = sbff1[j4 * 4 + 2], t3 = sbff1[j4 * 4 + 3];
            #pragma unroll
            for (int d = 0; d < 16; d++) {
                float4 w = *(const float4 *)(sWff1 + d * 64 + j4 * 4);
                float yd = y[d];
                t0 = fmaf(yd, w.x, t0); t1 = fmaf(yd, w.y, t1);
                t2 = fmaf(yd, w.z, t2); t3 = fmaf(yd, w.w, t3);
            }
            const float ISQ2 = 0.70710678118654752440f;
            float gs[4];
            gs[0] = 0.5f * t0 * (1.f + erff(t0 * ISQ2));
            gs[1] = 0.5f * t1 * (1.f + erff(t1 * ISQ2));
            gs[2] = 0.5f * t2 * (1.f + erff(t2 * ISQ2));
            gs[3] = 0.5f * t3 * (1.f + erff(t3 * ISQ2));
            #pragma unroll
            for (int jj = 0; jj < 4; jj++) {
                float gv = gs[jj];
                const float *w2 = sWff2 + (j4 * 4 + jj) * 16;
                #pragma unroll
                for (int d4 = 0; d4 < 4; d4++) {
                    float4 w = *(const float4 *)(w2 + d4 * 4);
                    acc[d4 * 4 + 0] = fmaf(gv, w.x, acc[d4 * 4 + 0]);
                    acc[d4 * 4 + 1] = fmaf(gv, w.y, acc[d4 * 4 + 1]);
                    acc[d4 * 4 + 2] = fmaf(gv, w.z, acc[d4 * 4 + 2]);
                    acc[d4 * 4 + 3] = fmaf(gv, w.w, acc[d4 * 4 + 3]);
                }
            }
        }
        #pragma unroll
        for (int d = 0; d < 16; d++) x[d] += acc[d] + sbff2[d];

        if (last) {
            float s = sbout;
            #pragma unroll
            for (int d = 0; d < 16; d++) s = fmaf(x[d], sWout[d], s);
            out[(size_t)b * NTOK + n] = s;
        } else {
            store16(xptr, x);
            passA_token(x, g_rot[n], sln1gN, sln1bN, sWqN, swqlN, st);
        }
    }
    if (!last) block_reduce_store(st, b, blockIdx.x);
}

// ---------------- launch ----------------
extern "C" void kernel_launch(void *const *d_in, const int *in_sizes, int n_in,
                              void *d_out, int out_size) {
    const float *corr  = (const float *)d_in[0];
    const float *Wemb  = (const float *)d_in[1];
    const float *bemb  = (const float *)d_in[2];
    const float *ln1g  = (const float *)d_in[3];
    const float *ln1b  = (const float *)d_in[4];
    const float *Wqkv  = (const float *)d_in[5];
    const float *wqlog = (const float *)d_in[6];
    const float *wklog = (const float *)d_in[7];
    const float *Wr    = (const float *)d_in[8];
    const float *br    = (const float *)d_in[9];
    const float *Wo    = (const float *)d_in[10];
    const float *bo    = (const float *)d_in[11];
    const float *ln2g  = (const float *)d_in[12];
    const float *ln2b  = (const float *)d_in[13];
    const float *Wff1  = (const float *)d_in[14];
    const float *bff1  = (const float *)d_in[15];
    const float *Wff2  = (const float *)d_in[16];
    const float *bff2  = (const float *)d_in[17];
    const float *Wout  = (const float *)d_in[18];
    const float *bout  = (const float *)d_in[19];
    float *out = (float *)d_out;
    (void)in_sizes; (void)n_in; (void)out_size;

    dim3 gridTok(CHUNKS, NBATCH);
    k_rot<<<(NTOK + 255) / 256, 256>>>();
    k_embed<<<gridTok, TPB>>>(corr, Wemb, bemb, ln1g, ln1b, Wqkv, wqlog);
    for (int i = 0; i < LAYERS; i++) {
        k_reduce<<<1, 128>>>(0);                                   // -> global_q
        k_passB<<<gridTok, TPB>>>(ln1g, ln1b, Wqkv, wklog, i);
        k_reduce<<<1, 128>>>(1);                                   // -> global_k
        k_passC<<<gridTok, TPB>>>(ln1g, ln1b, Wqkv, Wr, br, Wo, bo, ln2g, ln2b,
                                  Wff1, bff1, Wff2, bff2, wqlog, Wout, bout,
                                  out, i, i == LAYERS - 1 ? 1 : 0);
    }
}

// round 3
// speedup vs baseline: 2.1240x; 2.1240x over previous
#include <cuda_runtime.h>
#include <math.h>

#define LAYERS 6
#define DIM    16
#define NH     8
#define NBATCH 16
#define BOTD   26
#define NTOK   50625
#define CHUNKS 64
#define TPB    256
#define STRIDE (CHUNKS * TPB)
#define LN_EPS 1e-5f

// ---------------- static scratch ----------------
// x stored as 4 planes of float4 -> fully coalesced 512B/warp accesses
__device__ __align__(16) float4 g_x4[4][(size_t)NBATCH * NTOK];
__device__ __align__(16) float4 g_rot[NTOK];               // c0,s0,c1,s1
__device__ float g_part[NBATCH * CHUNKS * 40];             // per-block partials: 8 heads x (s,w0..w3)
__device__ float g_gq[NBATCH * NH * 4];
__device__ float g_gk[NBATCH * NH * 4];

// ---------------- helpers ----------------
__device__ __forceinline__ void load16s(size_t idx, float x[16]) {
    #pragma unroll
    for (int p = 0; p < 4; p++) {
        float4 v = g_x4[p][idx];
        x[p * 4] = v.x; x[p * 4 + 1] = v.y; x[p * 4 + 2] = v.z; x[p * 4 + 3] = v.w;
    }
}
__device__ __forceinline__ void store16s(size_t idx, const float x[16]) {
    #pragma unroll
    for (int p = 0; p < 4; p++)
        g_x4[p][idx] = make_float4(x[p * 4], x[p * 4 + 1], x[p * 4 + 2], x[p * 4 + 3]);
}

__device__ __forceinline__ void ln16(const float x[16], const float *g, const float *b, float y[16]) {
    float m = 0.f;
    #pragma unroll
    for (int d = 0; d < 16; d++) m += x[d];
    m *= 0.0625f;
    float v = 0.f;
    #pragma unroll
    for (int d = 0; d < 16; d++) { float t = x[d] - m; v = fmaf(t, t, v); }
    v *= 0.0625f;
    float inv = rsqrtf(v + LN_EPS);
    #pragma unroll
    for (int d = 0; d < 16; d++) y[d] = (x[d] - m) * inv * g[d] + b[d];
}

// y[16] . W[16x32] columns col..col+3 (W row-major, 32 wide, in smem)
__device__ __forceinline__ void dot16x4(const float y[16], const float *W, int col,
                                        float &o0, float &o1, float &o2, float &o3) {
    o0 = o1 = o2 = o3 = 0.f;
    #pragma unroll
    for (int d = 0; d < 16; d++) {
        float4 w = *(const float4 *)(W + d * 32 + col);
        float yd = y[d];
        o0 = fmaf(yd, w.x, o0); o1 = fmaf(yd, w.y, o1);
        o2 = fmaf(yd, w.z, o2); o3 = fmaf(yd, w.w, o3);
    }
}

// gelu(t) = 0.5 t (1 + erf(t/sqrt2)), erf via A&S 7.1.26 (|abs err| <= 1.5e-7)
__device__ __forceinline__ float gelu_exact(float t) {
    float xx = t * 0.70710678118654752440f;
    float a  = fabsf(xx);
    float u  = __fdividef(1.f, fmaf(0.3275911f, a, 1.f));
    float p  = u * (0.254829592f + u * (-0.284496736f + u * (1.421413741f +
               u * (-1.453152027f + u * 1.061405429f))));
    float er = 1.f - p * __expf(-a * a);
    er = copysignf(er, xx);
    return 0.5f * t * (1.f + er);
}

// plain-sum softmax accumulation (logits are tiny; no max subtraction needed)
__device__ __forceinline__ void sm_update(float &s, float w[4], float l,
                                          float a0, float a1, float a2, float a3) {
    float p = __expf(l);
    s += p;
    w[0] = fmaf(p, a0, w[0]); w[1] = fmaf(p, a1, w[1]);
    w[2] = fmaf(p, a2, w[2]); w[3] = fmaf(p, a3, w[3]);
}

// block reduce 8x(s,w0..w3) -> g_part[(b*CHUNKS+chunk)*40 + h*5 + f]
__device__ __forceinline__ void block_reduce_store(float sS[NH], float sW[NH][4],
                                                   int b, int chunk) {
    const unsigned FULL = 0xffffffffu;
    #pragma unroll
    for (int off = 16; off; off >>= 1) {
        #pragma unroll
        for (int h = 0; h < NH; h++) {
            sS[h]    += __shfl_xor_sync(FULL, sS[h],    off);
            sW[h][0] += __shfl_xor_sync(FULL, sW[h][0], off);
            sW[h][1] += __shfl_xor_sync(FULL, sW[h][1], off);
            sW[h][2] += __shfl_xor_sync(FULL, sW[h][2], off);
            sW[h][3] += __shfl_xor_sync(FULL, sW[h][3], off);
        }
    }
    __shared__ float sred[TPB / 32][40];
    int wid = threadIdx.x >> 5, lane = threadIdx.x & 31;
    if (lane == 0) {
        #pragma unroll
        for (int h = 0; h < NH; h++) {
            sred[wid][h * 5 + 0] = sS[h];
            sred[wid][h * 5 + 1] = sW[h][0]; sred[wid][h * 5 + 2] = sW[h][1];
            sred[wid][h * 5 + 3] = sW[h][2]; sred[wid][h * 5 + 4] = sW[h][3];
        }
    }
    __syncthreads();
    if (threadIdx.x < 40) {
        float acc = 0.f;
        #pragma unroll
        for (int w = 0; w < TPB / 32; w++) acc += sred[w][threadIdx.x];
        g_part[(size_t)(b * CHUNKS + chunk) * 40 + threadIdx.x] = acc;
    }
}

// pass-A body for one token: q logits + rotary aggr, plain-sum softmax
__device__ __forceinline__ void passA_token(const float x[16], float4 rt,
                                            const float *lg, const float *lb,
                                            const float *Wq, const float *wql,
                                            float sS[NH], float sW[NH][4]) {
    float y[16];
    ln16(x, lg, lb, y);
    #pragma unroll
    for (int h = 0; h < NH; h++) {
        float q0, q1, q2, q3;
        dot16x4(y, Wq, h * 4, q0, q1, q2, q3);
        float l = (q0 * wql[0] + q1 * wql[1] + q2 * wql[2] + q3 * wql[3]) * 0.5f;
        float a0 = q0 * rt.x - q1 * rt.y;
        float a1 = q1 * rt.x + q0 * rt.y;
        float a2 = q2 * rt.z - q3 * rt.w;
        float a3 = q3 * rt.z + q2 * rt.w;
        sm_update(sS[h], sW[h], l, a0, a1, a2, a3);
    }
}

// ---------------- kernels ----------------
__global__ void k_rot() {
    int n = blockIdx.x * blockDim.x + threadIdx.x;
    if (n >= NTOK) return;
    float t = (float)n;
    float s0, c0, s1, c1;
    sincosf(t * (float)M_PI, &s0, &c0);
    sincosf(t * (float)(5.0 * M_PI), &s1, &c1);
    g_rot[n] = make_float4(c0, s0, c1, s1);
}

// embedding + fused pass-A of layer 0
__global__ void __launch_bounds__(TPB, 2) k_embed(
    const float *__restrict__ corr, const float *__restrict__ Wemb, const float *__restrict__ bemb,
    const float *__restrict__ ln1g, const float *__restrict__ ln1b,
    const float *__restrict__ Wqkv, const float *__restrict__ wqlog) {
    __shared__ __align__(16) float sWemb[BOTD * DIM];
    __shared__ float sbemb[DIM], sln1g[DIM], sln1b[DIM], swql[4];
    __shared__ __align__(16) float sWq[DIM * 32];
    int tid = threadIdx.x;
    for (int i = tid; i < BOTD * DIM; i += TPB) sWemb[i] = Wemb[i];
    for (int i = tid; i < DIM; i += TPB) { sbemb[i] = bemb[i]; sln1g[i] = ln1g[i]; sln1b[i] = ln1b[i]; }
    for (int i = tid; i < DIM * 32; i += TPB) { int d = i >> 5, c = i & 31; sWq[i] = Wqkv[d * 96 + c]; }
    if (tid < 4) swql[tid] = wqlog[tid];
    __syncthreads();

    int b = blockIdx.y;
    const float *cb = corr + (size_t)b * BOTD * NTOK;
    float sS[NH], sW[NH][4];
    #pragma unroll
    for (int h = 0; h < NH; h++) { sS[h] = 0.f; sW[h][0] = sW[h][1] = sW[h][2] = sW[h][3] = 0.f; }

    for (int n = blockIdx.x * TPB + tid; n < NTOK; n += STRIDE) {
        float x[16];
        #pragma unroll
        for (int d = 0; d < 16; d++) x[d] = sbemb[d];
        #pragma unroll
        for (int c = 0; c < BOTD; c++) {
            float cv = fmaxf(cb[c * NTOK + n], 0.f);
            #pragma unroll
            for (int d4 = 0; d4 < 4; d4++) {
                float4 w = *(const float4 *)(sWemb + c * 16 + d4 * 4);
                x[d4 * 4 + 0] = fmaf(cv, w.x, x[d4 * 4 + 0]);
                x[d4 * 4 + 1] = fmaf(cv, w.y, x[d4 * 4 + 1]);
                x[d4 * 4 + 2] = fmaf(cv, w.z, x[d4 * 4 + 2]);
                x[d4 * 4 + 3] = fmaf(cv, w.w, x[d4 * 4 + 3]);
            }
        }
        store16s((size_t)b * NTOK + n, x);
        passA_token(x, g_rot[n], sln1g, sln1b, sWq, swql, sS, sW);
    }
    block_reduce_store(sS, sW, b, blockIdx.x);
}

// merge chunk partials -> global vector (which=0 -> g_gq, which=1 -> g_gk)
__global__ void k_reduce(int which) {
    int bh = threadIdx.x;
    if (bh >= NBATCH * NH) return;
    int b = bh >> 3, h = bh & 7;
    float s = 0.f, w0 = 0.f, w1 = 0.f, w2 = 0.f, w3 = 0.f;
    for (int c = 0; c < CHUNKS; c++) {
        const float *p = &g_part[(size_t)(b * CHUNKS + c) * 40 + h * 5];
        s += p[0]; w0 += p[1]; w1 += p[2]; w2 += p[3]; w3 += p[4];
    }
    float inv = 1.f / s;
    float *glob = which ? g_gk : g_gq;
    glob[bh * 4 + 0] = w0 * inv; glob[bh * 4 + 1] = w1 * inv;
    glob[bh * 4 + 2] = w2 * inv; glob[bh * 4 + 3] = w3 * inv;
}

// pass-B: k -> k2 logits -> plain-sum softmax of k_aggr
__global__ void __launch_bounds__(TPB, 3) k_passB(
    const float *__restrict__ ln1g_all, const float *__restrict__ ln1b_all,
    const float *__restrict__ Wqkv, const float *__restrict__ wklog_all, int layer) {
    __shared__ float sln1g[16], sln1b[16], swkl[2], sgq[NH * 4];
    __shared__ __align__(16) float sWk[DIM * 32];
    int tid = threadIdx.x, b = blockIdx.y;
    for (int i = tid; i < 16; i += TPB) { sln1g[i] = ln1g_all[layer * 16 + i]; sln1b[i] = ln1b_all[layer * 16 + i]; }
    for (int i = tid; i < 512; i += TPB) { int d = i >> 5, c = i & 31; sWk[i] = Wqkv[(layer * 16 + d) * 96 + 32 + c]; }
    if (tid < 2) swkl[tid] = wklog_all[layer * 2 + tid];
    for (int i = tid; i < 32; i += TPB) sgq[i] = g_gq[b * 32 + i];
    __syncthreads();

    float sS[NH], sW[NH][4];
    #pragma unroll
    for (int h = 0; h < NH; h++) { sS[h] = 0.f; sW[h][0] = sW[h][1] = sW[h][2] = sW[h][3] = 0.f; }

    for (int n = blockIdx.x * TPB + tid; n < NTOK; n += STRIDE) {
        float x[16], y[16];
        load16s((size_t)b * NTOK + n, x);
        ln16(x, sln1g, sln1b, y);
        float4 rt = g_rot[n];
        #pragma unroll
        for (int h = 0; h < NH; h++) {
            float k0, k1, k2v, k3;
            dot16x4(y, sWk, h * 4, k0, k1, k2v, k3);
            float ka = k0 * sgq[h * 4 + 0] + k1 * sgq[h * 4 + 1];
            float kb = k2v * sgq[h * 4 + 2] + k3 * sgq[h * 4 + 3];
            float l  = (ka * swkl[0] + kb * swkl[1]) * 0.5f;
            float a0 = k0 * rt.x - k1 * rt.y;
            float a1 = k1 * rt.x + k0 * rt.y;
            float a2 = k2v * rt.z - k3 * rt.w;
            float a3 = k3 * rt.z + k2v * rt.w;
            sm_update(sS[h], sW[h], l, a0, a1, a2, a3);
        }
    }
    block_reduce_store(sS, sW, b, blockIdx.x);
}

// pass-C: v->u->r->W_o->residual->LN2->FF->residual, fused with next layer pass-A
__global__ void __launch_bounds__(TPB, 2) k_passC(
    const float *__restrict__ ln1g_all, const float *__restrict__ ln1b_all,
    const float *__restrict__ Wqkv,
    const float *__restrict__ Wr_all, const float *__restrict__ br_all,
    const float *__restrict__ Wo_all, const float *__restrict__ bo_all,
    const float *__restrict__ ln2g_all, const float *__restrict__ ln2b_all,
    const float *__restrict__ Wff1_all, const float *__restrict__ bff1_all,
    const float *__restrict__ Wff2_all, const float *__restrict__ bff2_all,
    const float *__restrict__ wqlog_all,
    const float *__restrict__ Wout, const float *__restrict__ bout,
    float *__restrict__ out, int layer, int last) {
    __shared__ float sln1g[16], sln1b[16], sWr[8], sbr[4], sbo[16];
    __shared__ float sln2g[16], sln2b[16], sbff1[64], sbff2[16], sgk[32];
    __shared__ float sln1gN[16], sln1bN[16], swqlN[4], sWout[16], sbout;
    __shared__ __align__(16) float sWq[512], sWv[512], sWo[512];
    __shared__ __align__(16) float sWff1[1024], sWff2[1024], sWqN[512];
    int tid = threadIdx.x, b = blockIdx.y;

    for (int i = tid; i < 512; i += TPB) {
        int d = i >> 5, c = i & 31;
        sWq[i] = Wqkv[(layer * 16 + d) * 96 + c];
        sWv[i] = Wqkv[(layer * 16 + d) * 96 + 64 + c];
        sWo[i] = Wo_all[layer * 512 + i];
    }
    for (int i = tid; i < 1024; i += TPB) {
        sWff1[i] = Wff1_all[layer * 1024 + i];
        sWff2[i] = Wff2_all[layer * 1024 + i];
    }
    for (int i = tid; i < 64; i += TPB) sbff1[i] = bff1_all[layer * 64 + i];
    for (int i = tid; i < 16; i += TPB) {
        sln1g[i] = ln1g_all[layer * 16 + i]; sln1b[i] = ln1b_all[layer * 16 + i];
        sbo[i]   = bo_all[layer * 16 + i];
        sln2g[i] = ln2g_all[layer * 16 + i]; sln2b[i] = ln2b_all[layer * 16 + i];
        sbff2[i] = bff2_all[layer * 16 + i];
    }
    if (tid < 8) sWr[tid] = Wr_all[layer * 8 + tid];
    if (tid < 4) sbr[tid] = br_all[layer * 4 + tid];
    for (int i = tid; i < 32; i += TPB) sgk[i] = g_gk[b * 32 + i];
    if (!last) {
        int nl = layer + 1;
        for (int i = tid; i < 512; i += TPB) { int d = i >> 5, c = i & 31; sWqN[i] = Wqkv[(nl * 16 + d) * 96 + c]; }
        for (int i = tid; i < 16; i += TPB) { sln1gN[i] = ln1g_all[nl * 16 + i]; sln1bN[i] = ln1b_all[nl * 16 + i]; }
        if (tid < 4) swqlN[tid] = wqlog_all[nl * 4 + tid];
    } else {
        for (int i = tid; i < 16; i += TPB) sWout[i] = Wout[i];
        if (tid == 0) sbout = bout[0];
    }
    __syncthreads();

    float sS[NH], sWacc[NH][4];
    #pragma unroll
    for (int h = 0; h < NH; h++) { sS[h] = 0.f; sWacc[h][0] = sWacc[h][1] = sWacc[h][2] = sWacc[h][3] = 0.f; }

    for (int n = blockIdx.x * TPB + tid; n < NTOK; n += STRIDE) {
        float x[16], y[16];
        size_t idx = (size_t)b * NTOK + n;
        load16s(idx, x);
        ln16(x, sln1g, sln1b, y);

        // heads: q,v -> u -> r; accumulate output projection o inline (no r[32] array)
        float o[16];
        #pragma unroll
        for (int d = 0; d < 16; d++) o[d] = sbo[d];
        #pragma unroll
        for (int h = 0; h < NH; h++) {
            float q0, q1, q2, q3, v0, v1, v2, v3;
            dot16x4(y, sWq, h * 4, q0, q1, q2, q3);
            dot16x4(y, sWv, h * 4, v0, v1, v2, v3);
            float u0 = v0 * sgk[h * 4 + 0] + v1 * sgk[h * 4 + 1];
            float u1 = v2 * sgk[h * 4 + 2] + v3 * sgk[h * 4 + 3];
            float rc[4];
            rc[0] = u0 * sWr[0] + u1 * sWr[4] + sbr[0] + q0;
            rc[1] = u0 * sWr[1] + u1 * sWr[5] + sbr[1] + q1;
            rc[2] = u0 * sWr[2] + u1 * sWr[6] + sbr[2] + q2;
            rc[3] = u0 * sWr[3] + u1 * sWr[7] + sbr[3] + q3;
            #pragma unroll
            for (int j = 0; j < 4; j++) {
                float rcj = rc[j];
                const float *wrow = sWo + (h * 4 + j) * 16;
                #pragma unroll
                for (int d4 = 0; d4 < 4; d4++) {
                    float4 w = *(const float4 *)(wrow + d4 * 4);
                    o[d4 * 4 + 0] = fmaf(rcj, w.x, o[d4 * 4 + 0]);
                    o[d4 * 4 + 1] = fmaf(rcj, w.y, o[d4 * 4 + 1]);
                    o[d4 * 4 + 2] = fmaf(rcj, w.z, o[d4 * 4 + 2]);
                    o[d4 * 4 + 3] = fmaf(rcj, w.w, o[d4 * 4 + 3]);
                }
            }
        }
        #pragma unroll
        for (int d = 0; d < 16; d++) x[d] += o[d];

        // FF block
        ln16(x, sln2g, sln2b, y);
        float acc[16];
        #pragma unroll
        for (int d = 0; d < 16; d++) acc[d] = 0.f;
        #pragma unroll
        for (int j4 = 0; j4 < 16; j4++) {
            float t0 = sbff1[j4 * 4 + 0], t1 = sbff1[j4 * 4 + 1];
            float t2 = sbff1[j4 * 4 + 2], t3 = sbff1[j4 * 4 + 3];
            #pragma unroll
            for (int d = 0; d < 16; d++) {
                float4 w = *(const float4 *)(sWff1 + d * 64 + j4 * 4);
                float yd = y[d];
                t0 = fmaf(yd, w.x, t0); t1 = fmaf(yd, w.y, t1);
                t2 = fmaf(yd, w.z, t2); t3 = fmaf(yd, w.w, t3);
            }
            float gs[4];
            gs[0] = gelu_exact(t0); gs[1] = gelu_exact(t1);
            gs[2] = gelu_exact(t2); gs[3] = gelu_exact(t3);
            #pragma unroll
            for (int jj = 0; jj < 4; jj++) {
                float gv = gs[jj];
                const float *w2 = sWff2 + (j4 * 4 + jj) * 16;
                #pragma unroll
                for (int d4 = 0; d4 < 4; d4++) {
                    float4 w = *(const float4 *)(w2 + d4 * 4);
                    acc[d4 * 4 + 0] = fmaf(gv, w.x, acc[d4 * 4 + 0]);
                    acc[d4 * 4 + 1] = fmaf(gv, w.y, acc[d4 * 4 + 1]);
                    acc[d4 * 4 + 2] = fmaf(gv, w.z, acc[d4 * 4 + 2]);
                    acc[d4 * 4 + 3] = fmaf(gv, w.w, acc[d4 * 4 + 3]);
                }
            }
        }
        #pragma unroll
        for (int d = 0; d < 16; d++) x[d] += acc[d] + sbff2[d];

        if (last) {
            float s = sbout;
            #pragma unroll
            for (int d = 0; d < 16; d++) s = fmaf(x[d], sWout[d], s);
            out[idx] = s;
        } else {
            store16s(idx, x);
            passA_token(x, g_rot[n], sln1gN, sln1bN, sWqN, swqlN, sS, sWacc);
        }
    }
    if (!last) block_reduce_store(sS, sWacc, b, blockIdx.x);
}

// ---------------- launch ----------------
extern "C" void kernel_launch(void *const *d_in, const int *in_sizes, int n_in,
                              void *d_out, int out_size) {
    const float *corr  = (const float *)d_in[0];
    const float *Wemb  = (const float *)d_in[1];
    const float *bemb  = (const float *)d_in[2];
    const float *ln1g  = (const float *)d_in[3];
    const float *ln1b  = (const float *)d_in[4];
    const float *Wqkv  = (const float *)d_in[5];
    const float *wqlog = (const float *)d_in[6];
    const float *wklog = (const float *)d_in[7];
    const float *Wr    = (const float *)d_in[8];
    const float *br    = (const float *)d_in[9];
    const float *Wo    = (const float *)d_in[10];
    const float *bo    = (const float *)d_in[11];
    const float *ln2g  = (const float *)d_in[12];
    const float *ln2b  = (const float *)d_in[13];
    const float *Wff1  = (const float *)d_in[14];
    const float *bff1  = (const float *)d_in[15];
    const float *Wff2  = (const float *)d_in[16];
    const float *bff2  = (const float *)d_in[17];
    const float *Wout  = (const float *)d_in[18];
    const float *bout  = (const float *)d_in[19];
    float *out = (float *)d_out;
    (void)in_sizes; (void)n_in; (void)out_size;

    dim3 gridTok(CHUNKS, NBATCH);
    k_rot<<<(NTOK + 255) / 256, 256>>>();
    k_embed<<<gridTok, TPB>>>(corr, Wemb, bemb, ln1g, ln1b, Wqkv, wqlog);
    for (int i = 0; i < LAYERS; i++) {
        k_reduce<<<1, 128>>>(0);                                   // -> global_q
        k_passB<<<gridTok, TPB>>>(ln1g, ln1b, Wqkv, wklog, i);
        k_reduce<<<1, 128>>>(1);                                   // -> global_k
        k_passC<<<gridTok, TPB>>>(ln1g, ln1b, Wqkv, Wr, br, Wo, bo, ln2g, ln2b,
                                  Wff1, bff1, Wff2, bff2, wqlog, Wout, bout,
                                  out, i, i == LAYERS - 1 ? 1 : 0);
    }
}

// round 4
// speedup vs baseline: 5.8665x; 2.7620x over previous
#include <cuda_runtime.h>
#include <math.h>

#define LAYERS 6
#define DIM    16
#define NH     8
#define NBATCH 16
#define BOTD   26
#define NTOK   50625
#define TPB    256
#define UT     2                 // tokens per thread
#define SPAN   (TPB * UT)        // 512 tokens per block
#define NCH    99                // ceil(NTOK / SPAN)
#define LN_EPS 1e-5f

// ---------------- static scratch ----------------
__device__ __align__(16) float4 g_x4[4][(size_t)NBATCH * NTOK];   // x planes (SoA)
__device__ __align__(16) float4 g_rot[NTOK];                      // c0,s0,c1,s1
__device__ float g_part[(size_t)NBATCH * NCH * 40];               // 8 heads x (s,w0..w3)
__device__ float g_gq[NBATCH * NH * 4];
__device__ float g_gk[NBATCH * NH * 4];
// LN-folded weights (exact: ln gains are 1, biases 0, but computed generally)
__device__ float c_Wqkv[LAYERS][DIM * 96];
__device__ float c_bqkv[LAYERS][96];
__device__ float c_Wff1[LAYERS][DIM * 64];
__device__ float c_bff1[LAYERS][64];

// ---------------- helpers ----------------
__device__ __forceinline__ void load16s(size_t idx, float x[16]) {
    #pragma unroll
    for (int p = 0; p < 4; p++) {
        float4 v = g_x4[p][idx];
        x[p * 4] = v.x; x[p * 4 + 1] = v.y; x[p * 4 + 2] = v.z; x[p * 4 + 3] = v.w;
    }
}
__device__ __forceinline__ void store16s(size_t idx, const float x[16]) {
    #pragma unroll
    for (int p = 0; p < 4; p++)
        g_x4[p][idx] = make_float4(x[p * 4], x[p * 4 + 1], x[p * 4 + 2], x[p * 4 + 3]);
}

// z = (x - mean)*rsqrt(var+eps)   (LN with g,b folded into downstream weights)
__device__ __forceinline__ void lnz(const float x[16], float z[16]) {
    float m = 0.f;
    #pragma unroll
    for (int d = 0; d < 16; d++) m += x[d];
    m *= 0.0625f;
    float v = 0.f;
    #pragma unroll
    for (int d = 0; d < 16; d++) { float t = x[d] - m; v = fmaf(t, t, v); }
    v *= 0.0625f;
    float inv = rsqrtf(v + LN_EPS);
    #pragma unroll
    for (int d = 0; d < 16; d++) z[d] = (x[d] - m) * inv;
}

// two tokens share every weight load: out = bias + z @ W[:, col..col+3]
__device__ __forceinline__ void dot2(const float z0[16], const float z1[16],
                                     const float *W, const float *bias, int col,
                                     float o0[4], float o1[4]) {
    #pragma unroll
    for (int j = 0; j < 4; j++) { o0[j] = bias[col + j]; o1[j] = o0[j]; }
    #pragma unroll
    for (int d = 0; d < 16; d++) {
        float4 w = *(const float4 *)(W + d * 32 + col);
        float a = z0[d], b = z1[d];
        o0[0] = fmaf(a, w.x, o0[0]); o0[1] = fmaf(a, w.y, o0[1]);
        o0[2] = fmaf(a, w.z, o0[2]); o0[3] = fmaf(a, w.w, o0[3]);
        o1[0] = fmaf(b, w.x, o1[0]); o1[1] = fmaf(b, w.y, o1[1]);
        o1[2] = fmaf(b, w.z, o1[2]); o1[3] = fmaf(b, w.w, o1[3]);
    }
}

__device__ __forceinline__ float gelu_exact(float t) {
    float xx = t * 0.70710678118654752440f;
    float a  = fabsf(xx);
    float u  = __fdividef(1.f, fmaf(0.3275911f, a, 1.f));
    float p  = u * (0.254829592f + u * (-0.284496736f + u * (1.421413741f +
               u * (-1.453152027f + u * 1.061405429f))));
    float er = 1.f - p * __expf(-a * a);
    er = copysignf(er, xx);
    return 0.5f * t * (1.f + er);
}

__device__ __forceinline__ void sm_acc(float &s, float w[4], float l, float vmask,
                                       float a0, float a1, float a2, float a3) {
    float p = __expf(l) * vmask;
    s += p;
    w[0] = fmaf(p, a0, w[0]); w[1] = fmaf(p, a1, w[1]);
    w[2] = fmaf(p, a2, w[2]); w[3] = fmaf(p, a3, w[3]);
}

__device__ __forceinline__ void block_reduce_store(float sS[NH], float sW[NH][4],
                                                   int b, int chunk) {
    const unsigned FULL = 0xffffffffu;
    #pragma unroll
    for (int off = 16; off; off >>= 1) {
        #pragma unroll
        for (int h = 0; h < NH; h++) {
            sS[h]    += __shfl_xor_sync(FULL, sS[h],    off);
            sW[h][0] += __shfl_xor_sync(FULL, sW[h][0], off);
            sW[h][1] += __shfl_xor_sync(FULL, sW[h][1], off);
            sW[h][2] += __shfl_xor_sync(FULL, sW[h][2], off);
            sW[h][3] += __shfl_xor_sync(FULL, sW[h][3], off);
        }
    }
    __shared__ float sred[TPB / 32][40];
    int wid = threadIdx.x >> 5, lane = threadIdx.x & 31;
    if (lane == 0) {
        #pragma unroll
        for (int h = 0; h < NH; h++) {
            sred[wid][h * 5 + 0] = sS[h];
            sred[wid][h * 5 + 1] = sW[h][0]; sred[wid][h * 5 + 2] = sW[h][1];
            sred[wid][h * 5 + 3] = sW[h][2]; sred[wid][h * 5 + 4] = sW[h][3];
        }
    }
    __syncthreads();
    if (threadIdx.x < 40) {
        float acc = 0.f;
        #pragma unroll
        for (int w = 0; w < TPB / 32; w++) acc += sred[w][threadIdx.x];
        g_part[(size_t)(b * NCH + chunk) * 40 + threadIdx.x] = acc;
    }
}

// pass-A contribution of two tokens (q logits + rotary aggr)
__device__ __forceinline__ void passA2(const float x0[16], const float x1[16],
                                       float4 rt0, float4 rt1, float v0, float v1,
                                       const float *Wq, const float *bq, const float *wql,
                                       float sS[NH], float sW[NH][4]) {
    float z0[16], z1[16];
    lnz(x0, z0); lnz(x1, z1);
    #pragma unroll
    for (int h = 0; h < NH; h++) {
        float q0[4], q1[4];
        dot2(z0, z1, Wq, bq, h * 4, q0, q1);
        float l0 = (q0[0] * wql[0] + q0[1] * wql[1] + q0[2] * wql[2] + q0[3] * wql[3]) * 0.5f;
        float l1 = (q1[0] * wql[0] + q1[1] * wql[1] + q1[2] * wql[2] + q1[3] * wql[3]) * 0.5f;
        sm_acc(sS[h], sW[h], l0, v0,
               q0[0] * rt0.x - q0[1] * rt0.y, q0[1] * rt0.x + q0[0] * rt0.y,
               q0[2] * rt0.z - q0[3] * rt0.w, q0[3] * rt0.z + q0[2] * rt0.w);
        sm_acc(sS[h], sW[h], l1, v1,
               q1[0] * rt1.x - q1[1] * rt1.y, q1[1] * rt1.x + q1[0] * rt1.y,
               q1[2] * rt1.z - q1[3] * rt1.w, q1[3] * rt1.z + q1[2] * rt1.w);
    }
}

// ---------------- kernels ----------------
__global__ void k_rot() {
    int n = blockIdx.x * blockDim.x + threadIdx.x;
    if (n >= NTOK) return;
    float t = (float)n;
    float s0, c0, s1, c1;
    sincosf(t * (float)M_PI, &s0, &c0);
    sincosf(t * (float)(5.0 * M_PI), &s1, &c1);
    g_rot[n] = make_float4(c0, s0, c1, s1);
}

// fold LN g/b into W_qkv and W_ff1 (exact since g==1, b==0 in the data)
__global__ void k_prep(const float *__restrict__ ln1g, const float *__restrict__ ln1b,
                       const float *__restrict__ Wqkv,
                       const float *__restrict__ ln2g, const float *__restrict__ ln2b,
                       const float *__restrict__ Wff1, const float *__restrict__ bff1) {
    int tid = threadIdx.x;
    for (int i = tid; i < LAYERS * DIM * 96; i += blockDim.x) {
        int l = i / (DIM * 96), r = i % (DIM * 96), d = r / 96;
        c_Wqkv[l][r] = ln1g[l * 16 + d] * Wqkv[i];
    }
    for (int i = tid; i < LAYERS * 96; i += blockDim.x) {
        int l = i / 96, c = i % 96;
        float s = 0.f;
        for (int d = 0; d < 16; d++) s += ln1b[l * 16 + d] * Wqkv[(l * 16 + d) * 96 + c];
        c_bqkv[l][c] = s;
    }
    for (int i = tid; i < LAYERS * DIM * 64; i += blockDim.x) {
        int l = i / (DIM * 64), r = i % (DIM * 64), d = r / 64;
        c_Wff1[l][r] = ln2g[l * 16 + d] * Wff1[i];
    }
    for (int i = tid; i < LAYERS * 64; i += blockDim.x) {
        int l = i / 64, c = i % 64;
        float s = bff1[i];
        for (int d = 0; d < 16; d++) s += ln2b[l * 16 + d] * Wff1[(l * 16 + d) * 64 + c];
        c_bff1[l][c] = s;
    }
}

// embedding + fused pass-A of layer 0
__global__ void __launch_bounds__(TPB, 2) k_embed(
    const float *__restrict__ corr, const float *__restrict__ Wemb, const float *__restrict__ bemb,
    const float *__restrict__ wqlog) {
    __shared__ __align__(16) float sWemb[BOTD * DIM];
    __shared__ float sbemb[DIM], swql[4], sbq[32];
    __shared__ __align__(16) float sWq[DIM * 32];
    int tid = threadIdx.x, b = blockIdx.y;
    for (int i = tid; i < BOTD * DIM; i += TPB) sWemb[i] = Wemb[i];
    for (int i = tid; i < DIM; i += TPB) sbemb[i] = bemb[i];
    for (int i = tid; i < DIM * 32; i += TPB) { int d = i >> 5, c = i & 31; sWq[i] = c_Wqkv[0][d * 96 + c]; }
    for (int i = tid; i < 32; i += TPB) sbq[i] = c_bqkv[0][i];
    if (tid < 4) swql[tid] = wqlog[tid];
    __syncthreads();

    int n0 = blockIdx.x * SPAN + tid, n1 = n0 + TPB;
    float v0 = n0 < NTOK ? 1.f : 0.f, v1 = n1 < NTOK ? 1.f : 0.f;
    const float *cb = corr + (size_t)b * BOTD * NTOK;

    float x0[16], x1[16];
    #pragma unroll
    for (int d = 0; d < 16; d++) { x0[d] = sbemb[d]; x1[d] = sbemb[d]; }
    #pragma unroll 4
    for (int c = 0; c < BOTD; c++) {
        float c0 = v0 > 0.f ? fmaxf(cb[c * NTOK + n0], 0.f) : 0.f;
        float c1 = v1 > 0.f ? fmaxf(cb[c * NTOK + n1], 0.f) : 0.f;
        #pragma unroll
        for (int d4 = 0; d4 < 4; d4++) {
            float4 w = *(const float4 *)(sWemb + c * 16 + d4 * 4);
            x0[d4 * 4 + 0] = fmaf(c0, w.x, x0[d4 * 4 + 0]);
            x0[d4 * 4 + 1] = fmaf(c0, w.y, x0[d4 * 4 + 1]);
            x0[d4 * 4 + 2] = fmaf(c0, w.z, x0[d4 * 4 + 2]);
            x0[d4 * 4 + 3] = fmaf(c0, w.w, x0[d4 * 4 + 3]);
            x1[d4 * 4 + 0] = fmaf(c1, w.x, x1[d4 * 4 + 0]);
            x1[d4 * 4 + 1] = fmaf(c1, w.y, x1[d4 * 4 + 1]);
            x1[d4 * 4 + 2] = fmaf(c1, w.z, x1[d4 * 4 + 2]);
            x1[d4 * 4 + 3] = fmaf(c1, w.w, x1[d4 * 4 + 3]);
        }
    }
    if (v0 > 0.f) store16s((size_t)b * NTOK + n0, x0);
    if (v1 > 0.f) store16s((size_t)b * NTOK + n1, x1);
    float4 rt0 = v0 > 0.f ? g_rot[n0] : make_float4(1, 0, 1, 0);
    float4 rt1 = v1 > 0.f ? g_rot[n1] : make_float4(1, 0, 1, 0);

    float sS[NH], sW[NH][4];
    #pragma unroll
    for (int h = 0; h < NH; h++) { sS[h] = 0.f; sW[h][0] = sW[h][1] = sW[h][2] = sW[h][3] = 0.f; }
    passA2(x0, x1, rt0, rt1, v0, v1, sWq, sbq, swql, sS, sW);
    block_reduce_store(sS, sW, b, blockIdx.x);
}

// merge chunk partials and normalize -> g_gq (which=0) / g_gk (which=1)
__global__ void k_reduce(int which) {
    int b = blockIdx.x, tid = threadIdx.x;
    __shared__ float sf[40];
    if (tid < 320) {
        int f = tid >> 3, sub = tid & 7;
        float s = 0.f;
        for (int c = sub; c < NCH; c += 8)
            s += g_part[(size_t)(b * NCH + c) * 40 + f];
        #pragma unroll
        for (int o = 4; o; o >>= 1) s += __shfl_down_sync(0xffffffffu, s, o, 8);
        if (sub == 0) sf[f] = s;
    }
    __syncthreads();
    if (tid < 8) {
        float inv = 1.f / sf[tid * 5];
        float *glob = which ? g_gk : g_gq;
        #pragma unroll
        for (int c = 0; c < 4; c++)
            glob[b * 32 + tid * 4 + c] = sf[tid * 5 + 1 + c] * inv;
    }
}

// pass-B: k -> k2 logits -> softmax partials of k_aggr
__global__ void __launch_bounds__(TPB, 2) k_passB(
    const float *__restrict__ wklog_all, int layer) {
    __shared__ float swkl[2], sgq[32], sbk[32];
    __shared__ __align__(16) float sWk[DIM * 32];
    int tid = threadIdx.x, b = blockIdx.y;
    for (int i = tid; i < 512; i += TPB) { int d = i >> 5, c = i & 31; sWk[i] = c_Wqkv[layer][d * 96 + 32 + c]; }
    for (int i = tid; i < 32; i += TPB) { sbk[i] = c_bqkv[layer][32 + i]; sgq[i] = g_gq[b * 32 + i]; }
    if (tid < 2) swkl[tid] = wklog_all[layer * 2 + tid];
    __syncthreads();

    int n0 = blockIdx.x * SPAN + tid, n1 = n0 + TPB;
    float v0 = n0 < NTOK ? 1.f : 0.f, v1 = n1 < NTOK ? 1.f : 0.f;
    size_t base = (size_t)b * NTOK;
    float x0[16] = {0.f}, x1[16] = {0.f};
    if (v0 > 0.f) load16s(base + n0, x0);
    if (v1 > 0.f) load16s(base + n1, x1);
    float4 rt0 = v0 > 0.f ? g_rot[n0] : make_float4(1, 0, 1, 0);
    float4 rt1 = v1 > 0.f ? g_rot[n1] : make_float4(1, 0, 1, 0);

    float z0[16], z1[16];
    lnz(x0, z0); lnz(x1, z1);

    float sS[NH], sW[NH][4];
    #pragma unroll
    for (int h = 0; h < NH; h++) { sS[h] = 0.f; sW[h][0] = sW[h][1] = sW[h][2] = sW[h][3] = 0.f; }

    #pragma unroll
    for (int h = 0; h < NH; h++) {
        float k0[4], k1[4];
        dot2(z0, z1, sWk, sbk, h * 4, k0, k1);
        float g0 = sgq[h * 4 + 0], g1 = sgq[h * 4 + 1], g2 = sgq[h * 4 + 2], g3 = sgq[h * 4 + 3];
        float l0 = ((k0[0] * g0 + k0[1] * g1) * swkl[0] + (k0[2] * g2 + k0[3] * g3) * swkl[1]) * 0.5f;
        float l1 = ((k1[0] * g0 + k1[1] * g1) * swkl[0] + (k1[2] * g2 + k1[3] * g3) * swkl[1]) * 0.5f;
        sm_acc(sS[h], sW[h], l0, v0,
               k0[0] * rt0.x - k0[1] * rt0.y, k0[1] * rt0.x + k0[0] * rt0.y,
               k0[2] * rt0.z - k0[3] * rt0.w, k0[3] * rt0.z + k0[2] * rt0.w);
        sm_acc(sS[h], sW[h], l1, v1,
               k1[0] * rt1.x - k1[1] * rt1.y, k1[1] * rt1.x + k1[0] * rt1.y,
               k1[2] * rt1.z - k1[3] * rt1.w, k1[3] * rt1.z + k1[2] * rt1.w);
    }
    block_reduce_store(sS, sW, b, blockIdx.x);
}

// pass-C: v->u->r->W_o->residual->FF->residual, fused with next layer pass-A
__global__ void __launch_bounds__(TPB, 2) k_passC(
    const float *__restrict__ Wr_all, const float *__restrict__ br_all,
    const float *__restrict__ Wo_all, const float *__restrict__ bo_all,
    const float *__restrict__ Wff2_all, const float *__restrict__ bff2_all,
    const float *__restrict__ wqlog_all,
    const float *__restrict__ Wout, const float *__restrict__ bout,
    float *__restrict__ out, int layer, int last) {
    __shared__ float sWr[8], sbr[4], sbo[16], sbff1[64], sbff2[16], sgk[32];
    __shared__ float sbq[32], sbv[32], sbqN[32], swqlN[4], sWout[16], sbout;
    __shared__ __align__(16) float sWq[512], sWv[512], sWo[512];
    __shared__ __align__(16) float sWff1[1024], sWff2[1024], sWqN[512];
    int tid = threadIdx.x, b = blockIdx.y;

    for (int i = tid; i < 512; i += TPB) {
        int d = i >> 5, c = i & 31;
        sWq[i] = c_Wqkv[layer][d * 96 + c];
        sWv[i] = c_Wqkv[layer][d * 96 + 64 + c];
        sWo[i] = Wo_all[layer * 512 + i];
    }
    for (int i = tid; i < 1024; i += TPB) {
        sWff1[i] = c_Wff1[layer][i];
        sWff2[i] = Wff2_all[layer * 1024 + i];
    }
    for (int i = tid; i < 64; i += TPB) sbff1[i] = c_bff1[layer][i];
    for (int i = tid; i < 32; i += TPB) {
        sbq[i] = c_bqkv[layer][i]; sbv[i] = c_bqkv[layer][64 + i];
        sgk[i] = g_gk[b * 32 + i];
    }
    for (int i = tid; i < 16; i += TPB) {
        sbo[i] = bo_all[layer * 16 + i];
        sbff2[i] = bff2_all[layer * 16 + i];
    }
    if (tid < 8) sWr[tid] = Wr_all[layer * 8 + tid];
    if (tid < 4) sbr[tid] = br_all[layer * 4 + tid];
    if (!last) {
        int nl = layer + 1;
        for (int i = tid; i < 512; i += TPB) { int d = i >> 5, c = i & 31; sWqN[i] = c_Wqkv[nl][d * 96 + c]; }
        for (int i = tid; i < 32; i += TPB) sbqN[i] = c_bqkv[nl][i];
        if (tid < 4) swqlN[tid] = wqlog_all[nl * 4 + tid];
    } else {
        for (int i = tid; i < 16; i += TPB) sWout[i] = Wout[i];
        if (tid == 0) sbout = bout[0];
    }
    __syncthreads();

    int n0 = blockIdx.x * SPAN + tid, n1 = n0 + TPB;
    float v0 = n0 < NTOK ? 1.f : 0.f, v1 = n1 < NTOK ? 1.f : 0.f;
    size_t base = (size_t)b * NTOK;
    float x0[16] = {0.f}, x1[16] = {0.f};
    if (v0 > 0.f) load16s(base + n0, x0);
    if (v1 > 0.f) load16s(base + n1, x1);
    float4 rt0 = v0 > 0.f ? g_rot[n0] : make_float4(1, 0, 1, 0);
    float4 rt1 = v1 > 0.f ? g_rot[n1] : make_float4(1, 0, 1, 0);

    float z0[16], z1[16];
    lnz(x0, z0); lnz(x1, z1);

    // attention tail: q,v -> u -> r; accumulate W_o projection inline
    float o0[16], o1[16];
    #pragma unroll
    for (int d = 0; d < 16; d++) { o0[d] = sbo[d]; o1[d] = sbo[d]; }
    #pragma unroll
    for (int h = 0; h < NH; h++) {
        float q0[4], q1[4], vv0[4], vv1[4];
        dot2(z0, z1, sWq, sbq, h * 4, q0, q1);
        dot2(z0, z1, sWv, sbv, h * 4, vv0, vv1);
        float g0 = sgk[h * 4 + 0], g1 = sgk[h * 4 + 1], g2 = sgk[h * 4 + 2], g3 = sgk[h * 4 + 3];
        float u00 = vv0[0] * g0 + vv0[1] * g1, u01 = vv0[2] * g2 + vv0[3] * g3;
        float u10 = vv1[0] * g0 + vv1[1] * g1, u11 = vv1[2] * g2 + vv1[3] * g3;
        #pragma unroll
        for (int j = 0; j < 4; j++) {
            float rc0 = u00 * sWr[j] + u01 * sWr[4 + j] + sbr[j] + q0[j];
            float rc1 = u10 * sWr[j] + u11 * sWr[4 + j] + sbr[j] + q1[j];
            const float *wrow = sWo + (h * 4 + j) * 16;
            #pragma unroll
            for (int d4 = 0; d4 < 4; d4++) {
                float4 w = *(const float4 *)(wrow + d4 * 4);
                o0[d4 * 4 + 0] = fmaf(rc0, w.x, o0[d4 * 4 + 0]);
                o0[d4 * 4 + 1] = fmaf(rc0, w.y, o0[d4 * 4 + 1]);
                o0[d4 * 4 + 2] = fmaf(rc0, w.z, o0[d4 * 4 + 2]);
                o0[d4 * 4 + 3] = fmaf(rc0, w.w, o0[d4 * 4 + 3]);
                o1[d4 * 4 + 0] = fmaf(rc1, w.x, o1[d4 * 4 + 0]);
                o1[d4 * 4 + 1] = fmaf(rc1, w.y, o1[d4 * 4 + 1]);
                o1[d4 * 4 + 2] = fmaf(rc1, w.z, o1[d4 * 4 + 2]);
                o1[d4 * 4 + 3] = fmaf(rc1, w.w, o1[d4 * 4 + 3]);
            }
        }
    }
    #pragma unroll
    for (int d = 0; d < 16; d++) { x0[d] += o0[d]; x1[d] += o1[d]; }

    // FF block (LN2 folded into sWff1/sbff1)
    lnz(x0, z0); lnz(x1, z1);
    float a0[16], a1[16];
    #pragma unroll
    for (int d = 0; d < 16; d++) { a0[d] = 0.f; a1[d] = 0.f; }
    #pragma unroll
    for (int j4 = 0; j4 < 16; j4++) {
        float t00 = sbff1[j4 * 4 + 0], t01 = sbff1[j4 * 4 + 1];
        float t02 = sbff1[j4 * 4 + 2], t03 = sbff1[j4 * 4 + 3];
        float t10 = t00, t11 = t01, t12 = t02, t13 = t03;
        #pragma unroll
        for (int d = 0; d < 16; d++) {
            float4 w = *(const float4 *)(sWff1 + d * 64 + j4 * 4);
            float za = z0[d], zb = z1[d];
            t00 = fmaf(za, w.x, t00); t01 = fmaf(za, w.y, t01);
            t02 = fmaf(za, w.z, t02); t03 = fmaf(za, w.w, t03);
            t10 = fmaf(zb, w.x, t10); t11 = fmaf(zb, w.y, t11);
            t12 = fmaf(zb, w.z, t12); t13 = fmaf(zb, w.w, t13);
        }
        float gs0[4] = {gelu_exact(t00), gelu_exact(t01), gelu_exact(t02), gelu_exact(t03)};
        float gs1[4] = {gelu_exact(t10), gelu_exact(t11), gelu_exact(t12), gelu_exact(t13)};
        #pragma unroll
        for (int jj = 0; jj < 4; jj++) {
            const float *w2 = sWff2 + (j4 * 4 + jj) * 16;
            float ga = gs0[jj], gb = gs1[jj];
            #pragma unroll
            for (int d4 = 0; d4 < 4; d4++) {
                float4 w = *(const float4 *)(w2 + d4 * 4);
                a0[d4 * 4 + 0] = fmaf(ga, w.x, a0[d4 * 4 + 0]);
                a0[d4 * 4 + 1] = fmaf(ga, w.y, a0[d4 * 4 + 1]);
                a0[d4 * 4 + 2] = fmaf(ga, w.z, a0[d4 * 4 + 2]);
                a0[d4 * 4 + 3] = fmaf(ga, w.w, a0[d4 * 4 + 3]);
                a1[d4 * 4 + 0] = fmaf(gb, w.x, a1[d4 * 4 + 0]);
                a1[d4 * 4 + 1] = fmaf(gb, w.y, a1[d4 * 4 + 1]);
                a1[d4 * 4 + 2] = fmaf(gb, w.z, a1[d4 * 4 + 2]);
                a1[d4 * 4 + 3] = fmaf(gb, w.w, a1[d4 * 4 + 3]);
            }
        }
    }
    #pragma unroll
    for (int d = 0; d < 16; d++) { x0[d] += a0[d] + sbff2[d]; x1[d] += a1[d] + sbff2[d]; }

    if (last) {
        float s0 = sbout, s1 = sbout;
        #pragma unroll
        for (int d = 0; d < 16; d++) { s0 = fmaf(x0[d], sWout[d], s0); s1 = fmaf(x1[d], sWout[d], s1); }
        if (v0 > 0.f) out[base + n0] = s0;
        if (v1 > 0.f) out[base + n1] = s1;
    } else {
        if (v0 > 0.f) store16s(base + n0, x0);
        if (v1 > 0.f) store16s(base + n1, x1);
        float sS[NH], sW[NH][4];
        #pragma unroll
        for (int h = 0; h < NH; h++) { sS[h] = 0.f; sW[h][0] = sW[h][1] = sW[h][2] = sW[h][3] = 0.f; }
        passA2(x0, x1, rt0, rt1, v0, v1, sWqN, sbqN, swqlN, sS, sW);
        block_reduce_store(sS, sW, b, blockIdx.x);
    }
}

// ---------------- launch ----------------
extern "C" void kernel_launch(void *const *d_in, const int *in_sizes, int n_in,
                              void *d_out, int out_size) {
    const float *corr  = (const float *)d_in[0];
    const float *Wemb  = (const float *)d_in[1];
    const float *bemb  = (const float *)d_in[2];
    const float *ln1g  = (const float *)d_in[3];
    const float *ln1b  = (const float *)d_in[4];
    const float *Wqkv  = (const float *)d_in[5];
    const float *wqlog = (const float *)d_in[6];
    const float *wklog = (const float *)d_in[7];
    const float *Wr    = (const float *)d_in[8];
    const float *br    = (const float *)d_in[9];
    const float *Wo    = (const float *)d_in[10];
    const float *bo    = (const float *)d_in[11];
    const float *ln2g  = (const float *)d_in[12];
    const float *ln2b  = (const float *)d_in[13];
    const float *Wff1  = (const float *)d_in[14];
    const float *bff1  = (const float *)d_in[15];
    const float *Wff2  = (const float *)d_in[16];
    const float *bff2  = (const float *)d_in[17];
    const float *Wout  = (const float *)d_in[18];
    const float *bout  = (const float *)d_in[19];
    float *out = (float *)d_out;
    (void)in_sizes; (void)n_in; (void)out_size;

    dim3 gridTok(NCH, NBATCH);
    k_prep<<<1, 256>>>(ln1g, ln1b, Wqkv, ln2g, ln2b, Wff1, bff1);
    k_rot<<<(NTOK + 255) / 256, 256>>>();
    k_embed<<<gridTok, TPB>>>(corr, Wemb, bemb, wqlog);
    for (int i = 0; i < LAYERS; i++) {
        k_reduce<<<NBATCH, 512>>>(0);                              // -> global_q
        k_passB<<<gridTok, TPB>>>(wklog, i);
        k_reduce<<<NBATCH, 512>>>(1);                              // -> global_k
        k_passC<<<gridTok, TPB>>>(Wr, br, Wo, bo, Wff2, bff2, wqlog, Wout, bout,
                                  out, i, i == LAYERS - 1 ? 1 : 0);
    }
}

// round 5
// speedup vs baseline: 6.2346x; 1.0628x over previous
#include <cuda_runtime.h>
#include <math.h>

#define LAYERS 6
#define DIM    16
#define NH     8
#define NBATCH 16
#define BOTD   26
#define NTOK   50625
#define TPB    256
#define UT     2                 // tokens per thread
#define SPAN   (TPB * UT)        // 512 tokens per block
#define NCH    99                // ceil(NTOK / SPAN)
#define LN_EPS 1e-5f

typedef unsigned long long u64;

// ---------------- static scratch ----------------
__device__ __align__(16) float4 g_x4[4][(size_t)NBATCH * NTOK];   // x planes (SoA)
__device__ __align__(16) float4 g_rot[NTOK];                      // c0,s0,c1,s1
// double-buffered softmax partials: buf0 = q-partials, buf1 = k-partials
__device__ float g_part[2][(size_t)NBATCH * NCH * 40];
// LN-folded weights
__device__ __align__(16) float c_Wqkv[LAYERS][DIM * 96];
__device__ __align__(16) float c_bqkv[LAYERS][96];
__device__ __align__(16) float c_Wff1[LAYERS][DIM * 64];
__device__ __align__(16) float c_bff1[LAYERS][64];

// ---------------- f32x2 packed helpers ----------------
__device__ __forceinline__ u64 pack2(float x, float y) {
    u64 r; asm("mov.b64 %0, {%1, %2};" : "=l"(r) : "f"(x), "f"(y)); return r;
}
__device__ __forceinline__ void unpack2(u64 v, float &x, float &y) {
    asm("mov.b64 {%0, %1}, %2;" : "=f"(x), "=f"(y) : "l"(v));
}
__device__ __forceinline__ u64 ffma2(u64 a, u64 b, u64 c) {
    u64 r; asm("fma.rn.f32x2 %0, %1, %2, %3;" : "=l"(r) : "l"(a), "l"(b), "l"(c)); return r;
}

// ---------------- helpers ----------------
__device__ __forceinline__ void load16s(size_t idx, float x[16]) {
    #pragma unroll
    for (int p = 0; p < 4; p++) {
        float4 v = g_x4[p][idx];
        x[p * 4] = v.x; x[p * 4 + 1] = v.y; x[p * 4 + 2] = v.z; x[p * 4 + 3] = v.w;
    }
}
__device__ __forceinline__ void store16s(size_t idx, const float x[16]) {
    #pragma unroll
    for (int p = 0; p < 4; p++)
        g_x4[p][idx] = make_float4(x[p * 4], x[p * 4 + 1], x[p * 4 + 2], x[p * 4 + 3]);
}

// z = (x-mean)*rsqrt(var+eps), then broadcast-pack each lane
__device__ __forceinline__ void lnz_pack(const float x[16], u64 zp[16]) {
    float m = 0.f;
    #pragma unroll
    for (int d = 0; d < 16; d++) m += x[d];
    m *= 0.0625f;
    float v = 0.f;
    #pragma unroll
    for (int d = 0; d < 16; d++) { float t = x[d] - m; v = fmaf(t, t, v); }
    v *= 0.0625f;
    float inv = rsqrtf(v + LN_EPS);
    #pragma unroll
    for (int d = 0; d < 16; d++) { float z = (x[d] - m) * inv; zp[d] = pack2(z, z); }
}

// packed dual-token 16x4 dot: out = bias + z @ W[:, col..col+3]
__device__ __forceinline__ void dot2p(const u64 zp0[16], const u64 zp1[16],
                                      const float *W, const float *bias, int col,
                                      float k0[4], float k1[4]) {
    u64 a0 = *(const u64 *)(bias + col), b0 = *(const u64 *)(bias + col + 2);
    u64 a1 = a0, b1 = b0;
    #pragma unroll
    for (int d = 0; d < 16; d++) {
        ulonglong2 w = *(const ulonglong2 *)(W + d * 32 + col);
        a0 = ffma2(zp0[d], w.x, a0); b0 = ffma2(zp0[d], w.y, b0);
        a1 = ffma2(zp1[d], w.x, a1); b1 = ffma2(zp1[d], w.y, b1);
    }
    unpack2(a0, k0[0], k0[1]); unpack2(b0, k0[2], k0[3]);
    unpack2(a1, k1[0], k1[1]); unpack2(b1, k1[2], k1[3]);
}

__device__ __forceinline__ float gelu_exact(float t) {
    float xx = t * 0.70710678118654752440f;
    float a  = fabsf(xx);
    float u  = __fdividef(1.f, fmaf(0.3275911f, a, 1.f));
    float p  = u * (0.254829592f + u * (-0.284496736f + u * (1.421413741f +
               u * (-1.453152027f + u * 1.061405429f))));
    float er = 1.f - p * __expf(-a * a);
    er = copysignf(er, xx);
    return 0.5f * t * (1.f + er);
}

__device__ __forceinline__ void sm_acc(float &s, float w[4], float l, float vmask,
                                       float a0, float a1, float a2, float a3) {
    float p = __expf(l) * vmask;
    s += p;
    w[0] = fmaf(p, a0, w[0]); w[1] = fmaf(p, a1, w[1]);
    w[2] = fmaf(p, a2, w[2]); w[3] = fmaf(p, a3, w[3]);
}

__device__ __forceinline__ void block_reduce_store(float sS[NH], float sW[NH][4],
                                                   int b, int chunk, int buf) {
    const unsigned FULL = 0xffffffffu;
    #pragma unroll
    for (int off = 16; off; off >>= 1) {
        #pragma unroll
        for (int h = 0; h < NH; h++) {
            sS[h]    += __shfl_xor_sync(FULL, sS[h],    off);
            sW[h][0] += __shfl_xor_sync(FULL, sW[h][0], off);
            sW[h][1] += __shfl_xor_sync(FULL, sW[h][1], off);
            sW[h][2] += __shfl_xor_sync(FULL, sW[h][2], off);
            sW[h][3] += __shfl_xor_sync(FULL, sW[h][3], off);
        }
    }
    __shared__ float sred[TPB / 32][40];
    int wid = threadIdx.x >> 5, lane = threadIdx.x & 31;
    if (lane == 0) {
        #pragma unroll
        for (int h = 0; h < NH; h++) {
            sred[wid][h * 5 + 0] = sS[h];
            sred[wid][h * 5 + 1] = sW[h][0]; sred[wid][h * 5 + 2] = sW[h][1];
            sred[wid][h * 5 + 3] = sW[h][2]; sred[wid][h * 5 + 4] = sW[h][3];
        }
    }
    __syncthreads();
    if (threadIdx.x < 40) {
        float acc = 0.f;
        #pragma unroll
        for (int w = 0; w < TPB / 32; w++) acc += sred[w][threadIdx.x];
        g_part[buf][(size_t)(b * NCH + chunk) * 40 + threadIdx.x] = acc;
    }
}

// prologue: reduce this batch's partials (buf) into normalized global vector sg[32]
__device__ __forceinline__ void reduce_global(int b, int buf, float sg[32]) {
    __shared__ float spart[6][40];
    int tid = threadIdx.x;
    if (tid < 240) {
        int sub = tid / 40, f = tid % 40;
        float s = 0.f;
        for (int c = sub; c < NCH; c += 6)
            s += g_part[buf][(size_t)(b * NCH + c) * 40 + f];
        spart[sub][f] = s;
    }
    __syncthreads();
    if (tid < 8) {
        float s = 0.f;
        #pragma unroll
        for (int k = 0; k < 6; k++) s += spart[k][tid * 5];
        float inv = 1.f / s;
        #pragma unroll
        for (int j = 0; j < 4; j++) {
            float w = 0.f;
            #pragma unroll
            for (int k = 0; k < 6; k++) w += spart[k][tid * 5 + 1 + j];
            sg[tid * 4 + j] = w * inv;
        }
    }
    __syncthreads();
}

// pass-A contribution of two tokens (q logits + rotary aggr), packed math
__device__ __forceinline__ void passA2(const u64 zp0[16], const u64 zp1[16],
                                       float4 rt0, float4 rt1, float v0, float v1,
                                       const float *Wq, const float *bq, const float *wql,
                                       float sS[NH], float sW[NH][4]) {
    #pragma unroll
    for (int h = 0; h < NH; h++) {
        float q0[4], q1[4];
        dot2p(zp0, zp1, Wq, bq, h * 4, q0, q1);
        float l0 = (q0[0] * wql[0] + q0[1] * wql[1] + q0[2] * wql[2] + q0[3] * wql[3]) * 0.5f;
        float l1 = (q1[0] * wql[0] + q1[1] * wql[1] + q1[2] * wql[2] + q1[3] * wql[3]) * 0.5f;
        sm_acc(sS[h], sW[h], l0, v0,
               q0[0] * rt0.x - q0[1] * rt0.y, q0[1] * rt0.x + q0[0] * rt0.y,
               q0[2] * rt0.z - q0[3] * rt0.w, q0[3] * rt0.z + q0[2] * rt0.w);
        sm_acc(sS[h], sW[h], l1, v1,
               q1[0] * rt1.x - q1[1] * rt1.y, q1[1] * rt1.x + q1[0] * rt1.y,
               q1[2] * rt1.z - q1[3] * rt1.w, q1[3] * rt1.z + q1[2] * rt1.w);
    }
}

// ---------------- kernels ----------------
__global__ void k_rot() {
    int n = blockIdx.x * blockDim.x + threadIdx.x;
    if (n >= NTOK) return;
    float t = (float)n;
    float s0, c0, s1, c1;
    sincosf(t * (float)M_PI, &s0, &c0);
    sincosf(t * (float)(5.0 * M_PI), &s1, &c1);
    g_rot[n] = make_float4(c0, s0, c1, s1);
}

// fold LN g/b into W_qkv and W_ff1 (exact since g==1, b==0 in the data)
__global__ void k_prep(const float *__restrict__ ln1g, const float *__restrict__ ln1b,
                       const float *__restrict__ Wqkv,
                       const float *__restrict__ ln2g, const float *__restrict__ ln2b,
                       const float *__restrict__ Wff1, const float *__restrict__ bff1) {
    int tid = threadIdx.x;
    for (int i = tid; i < LAYERS * DIM * 96; i += blockDim.x) {
        int l = i / (DIM * 96), r = i % (DIM * 96), d = r / 96;
        c_Wqkv[l][r] = ln1g[l * 16 + d] * Wqkv[i];
    }
    for (int i = tid; i < LAYERS * 96; i += blockDim.x) {
        int l = i / 96, c = i % 96;
        float s = 0.f;
        for (int d = 0; d < 16; d++) s += ln1b[l * 16 + d] * Wqkv[(l * 16 + d) * 96 + c];
        c_bqkv[l][c] = s;
    }
    for (int i = tid; i < LAYERS * DIM * 64; i += blockDim.x) {
        int l = i / (DIM * 64), r = i % (DIM * 64), d = r / 64;
        c_Wff1[l][r] = ln2g[l * 16 + d] * Wff1[i];
    }
    for (int i = tid; i < LAYERS * 64; i += blockDim.x) {
        int l = i / 64, c = i % 64;
        float s = bff1[i];
        for (int d = 0; d < 16; d++) s += ln2b[l * 16 + d] * Wff1[(l * 16 + d) * 64 + c];
        c_bff1[l][c] = s;
    }
}

// embedding + fused pass-A of layer 0 (writes q-partials into buf 0)
__global__ void __launch_bounds__(TPB, 2) k_embed(
    const float *__restrict__ corr, const float *__restrict__ Wemb, const float *__restrict__ bemb,
    const float *__restrict__ wqlog) {
    __shared__ __align__(16) float sWemb[BOTD * DIM];
    __shared__ __align__(16) float sbemb[DIM], sbq[32];
    __shared__ float swql[4];
    __shared__ __align__(16) float sWq[DIM * 32];
    int tid = threadIdx.x, b = blockIdx.y;
    for (int i = tid; i < BOTD * DIM; i += TPB) sWemb[i] = Wemb[i];
    for (int i = tid; i < DIM; i += TPB) sbemb[i] = bemb[i];
    for (int i = tid; i < DIM * 32; i += TPB) { int d = i >> 5, c = i & 31; sWq[i] = c_Wqkv[0][d * 96 + c]; }
    for (int i = tid; i < 32; i += TPB) sbq[i] = c_bqkv[0][i];
    if (tid < 4) swql[tid] = wqlog[tid];
    __syncthreads();

    int n0 = blockIdx.x * SPAN + tid, n1 = n0 + TPB;
    float v0 = n0 < NTOK ? 1.f : 0.f, v1 = n1 < NTOK ? 1.f : 0.f;
    const float *cb = corr + (size_t)b * BOTD * NTOK;

    u64 x0p[8], x1p[8];
    #pragma unroll
    for (int j = 0; j < 8; j++) { x0p[j] = *(const u64 *)(sbemb + j * 2); x1p[j] = x0p[j]; }
    #pragma unroll 2
    for (int c = 0; c < BOTD; c++) {
        float c0 = v0 > 0.f ? fmaxf(cb[c * NTOK + n0], 0.f) : 0.f;
        float c1 = v1 > 0.f ? fmaxf(cb[c * NTOK + n1], 0.f) : 0.f;
        u64 c0p = pack2(c0, c0), c1p = pack2(c1, c1);
        #pragma unroll
        for (int j4 = 0; j4 < 4; j4++) {
            ulonglong2 w = *(const ulonglong2 *)(sWemb + c * 16 + j4 * 4);
            x0p[j4 * 2]     = ffma2(c0p, w.x, x0p[j4 * 2]);
            x0p[j4 * 2 + 1] = ffma2(c0p, w.y, x0p[j4 * 2 + 1]);
            x1p[j4 * 2]     = ffma2(c1p, w.x, x1p[j4 * 2]);
            x1p[j4 * 2 + 1] = ffma2(c1p, w.y, x1p[j4 * 2 + 1]);
        }
    }
    float x0[16], x1[16];
    #pragma unroll
    for (int j = 0; j < 8; j++) {
        unpack2(x0p[j], x0[j * 2], x0[j * 2 + 1]);
        unpack2(x1p[j], x1[j * 2], x1[j * 2 + 1]);
    }
    if (v0 > 0.f) store16s((size_t)b * NTOK + n0, x0);
    if (v1 > 0.f) store16s((size_t)b * NTOK + n1, x1);
    float4 rt0 = v0 > 0.f ? g_rot[n0] : make_float4(1, 0, 1, 0);
    float4 rt1 = v1 > 0.f ? g_rot[n1] : make_float4(1, 0, 1, 0);

    u64 zp0[16], zp1[16];
    lnz_pack(x0, zp0); lnz_pack(x1, zp1);
    float sS[NH], sW[NH][4];
    #pragma unroll
    for (int h = 0; h < NH; h++) { sS[h] = 0.f; sW[h][0] = sW[h][1] = sW[h][2] = sW[h][3] = 0.f; }
    passA2(zp0, zp1, rt0, rt1, v0, v1, sWq, sbq, swql, sS, sW);
    block_reduce_store(sS, sW, b, blockIdx.x, 0);
}

// pass-B: reduce q-partials (buf0) -> global_q; k logits -> k-partials (buf1)
__global__ void __launch_bounds__(TPB, 2) k_passB(
    const float *__restrict__ wklog_all, int layer) {
    __shared__ float swkl[2], sgq[32];
    __shared__ __align__(16) float sbk[32];
    __shared__ __align__(16) float sWk[DIM * 32];
    int tid = threadIdx.x, b = blockIdx.y;
    for (int i = tid; i < 512; i += TPB) { int d = i >> 5, c = i & 31; sWk[i] = c_Wqkv[layer][d * 96 + 32 + c]; }
    for (int i = tid; i < 32; i += TPB) sbk[i] = c_bqkv[layer][32 + i];
    if (tid < 2) swkl[tid] = wklog_all[layer * 2 + tid];
    reduce_global(b, 0, sgq);           // includes the needed __syncthreads()

    int n0 = blockIdx.x * SPAN + tid, n1 = n0 + TPB;
    float v0 = n0 < NTOK ? 1.f : 0.f, v1 = n1 < NTOK ? 1.f : 0.f;
    size_t base = (size_t)b * NTOK;
    float x0[16] = {0.f}, x1[16] = {0.f};
    if (v0 > 0.f) load16s(base + n0, x0);
    if (v1 > 0.f) load16s(base + n1, x1);
    float4 rt0 = v0 > 0.f ? g_rot[n0] : make_float4(1, 0, 1, 0);
    float4 rt1 = v1 > 0.f ? g_rot[n1] : make_float4(1, 0, 1, 0);

    u64 zp0[16], zp1[16];
    lnz_pack(x0, zp0); lnz_pack(x1, zp1);

    float sS[NH], sW[NH][4];
    #pragma unroll
    for (int h = 0; h < NH; h++) { sS[h] = 0.f; sW[h][0] = sW[h][1] = sW[h][2] = sW[h][3] = 0.f; }

    #pragma unroll
    for (int h = 0; h < NH; h++) {
        float k0[4], k1[4];
        dot2p(zp0, zp1, sWk, sbk, h * 4, k0, k1);
        float g0 = sgq[h * 4 + 0], g1 = sgq[h * 4 + 1], g2 = sgq[h * 4 + 2], g3 = sgq[h * 4 + 3];
        float l0 = ((k0[0] * g0 + k0[1] * g1) * swkl[0] + (k0[2] * g2 + k0[3] * g3) * swkl[1]) * 0.5f;
        float l1 = ((k1[0] * g0 + k1[1] * g1) * swkl[0] + (k1[2] * g2 + k1[3] * g3) * swkl[1]) * 0.5f;
        sm_acc(sS[h], sW[h], l0, v0,
               k0[0] * rt0.x - k0[1] * rt0.y, k0[1] * rt0.x + k0[0] * rt0.y,
               k0[2] * rt0.z - k0[3] * rt0.w, k0[3] * rt0.z + k0[2] * rt0.w);
        sm_acc(sS[h], sW[h], l1, v1,
               k1[0] * rt1.x - k1[1] * rt1.y, k1[1] * rt1.x + k1[0] * rt1.y,
               k1[2] * rt1.z - k1[3] * rt1.w, k1[3] * rt1.z + k1[2] * rt1.w);
    }
    block_reduce_store(sS, sW, b, blockIdx.x, 1);
}

// pass-C: reduce k-partials (buf1) -> global_k; tail + FF + next pass-A (buf0)
__global__ void __launch_bounds__(TPB, 2) k_passC(
    const float *__restrict__ Wr_all, const float *__restrict__ br_all,
    const float *__restrict__ Wo_all, const float *__restrict__ bo_all,
    const float *__restrict__ Wff2_all, const float *__restrict__ bff2_all,
    const float *__restrict__ wqlog_all,
    const float *__restrict__ Wout, const float *__restrict__ bout,
    float *__restrict__ out, int layer, int last) {
    __shared__ float sWr[8], sbr[4], sgk[32], swqlN[4], sWout[16], sbout;
    __shared__ __align__(16) float sbo[16], sbff1[64], sbff2[16], sbq[32], sbv[32], sbqN[32];
    __shared__ __align__(16) float sWq[512], sWv[512], sWo[512];
    __shared__ __align__(16) float sWff1[1024], sWff2[1024], sWqN[512];
    int tid = threadIdx.x, b = blockIdx.y;

    for (int i = tid; i < 512; i += TPB) {
        int d = i >> 5, c = i & 31;
        sWq[i] = c_Wqkv[layer][d * 96 + c];
        sWv[i] = c_Wqkv[layer][d * 96 + 64 + c];
        sWo[i] = Wo_all[layer * 512 + i];
    }
    for (int i = tid; i < 1024; i += TPB) {
        sWff1[i] = c_Wff1[layer][i];
        sWff2[i] = Wff2_all[layer * 1024 + i];
    }
    for (int i = tid; i < 64; i += TPB) sbff1[i] = c_bff1[layer][i];
    for (int i = tid; i < 32; i += TPB) { sbq[i] = c_bqkv[layer][i]; sbv[i] = c_bqkv[layer][64 + i]; }
    for (int i = tid; i < 16; i += TPB) {
        sbo[i] = bo_all[layer * 16 + i];
        sbff2[i] = bff2_all[layer * 16 + i];
    }
    if (tid < 8) sWr[tid] = Wr_all[layer * 8 + tid];
    if (tid < 4) sbr[tid] = br_all[layer * 4 + tid];
    if (!last) {
        int nl = layer + 1;
        for (int i = tid; i < 512; i += TPB) { int d = i >> 5, c = i & 31; sWqN[i] = c_Wqkv[nl][d * 96 + c]; }
        for (int i = tid; i < 32; i += TPB) sbqN[i] = c_bqkv[nl][i];
        if (tid < 4) swqlN[tid] = wqlog_all[nl * 4 + tid];
    } else {
        for (int i = tid; i < 16; i += TPB) sWout[i] = Wout[i];
        if (tid == 0) sbout = bout[0];
    }
    reduce_global(b, 1, sgk);           // includes the needed __syncthreads()

    int n0 = blockIdx.x * SPAN + tid, n1 = n0 + TPB;
    float v0 = n0 < NTOK ? 1.f : 0.f, v1 = n1 < NTOK ? 1.f : 0.f;
    size_t base = (size_t)b * NTOK;
    float x0[16] = {0.f}, x1[16] = {0.f};
    if (v0 > 0.f) load16s(base + n0, x0);
    if (v1 > 0.f) load16s(base + n1, x1);
    float4 rt0 = v0 > 0.f ? g_rot[n0] : make_float4(1, 0, 1, 0);
    float4 rt1 = v1 > 0.f ? g_rot[n1] : make_float4(1, 0, 1, 0);

    u64 zp0[16], zp1[16];
    lnz_pack(x0, zp0); lnz_pack(x1, zp1);

    // attention tail: q,v -> u -> r; accumulate W_o projection inline (packed)
    u64 o0p[8], o1p[8];
    #pragma unroll
    for (int j = 0; j < 8; j++) { o0p[j] = *(const u64 *)(sbo + j * 2); o1p[j] = o0p[j]; }
    #pragma unroll
    for (int h = 0; h < NH; h++) {
        float q0[4], q1[4], vv0[4], vv1[4];
        dot2p(zp0, zp1, sWq, sbq, h * 4, q0, q1);
        dot2p(zp0, zp1, sWv, sbv, h * 4, vv0, vv1);
        float g0 = sgk[h * 4 + 0], g1 = sgk[h * 4 + 1], g2 = sgk[h * 4 + 2], g3 = sgk[h * 4 + 3];
        float u00 = vv0[0] * g0 + vv0[1] * g1, u01 = vv0[2] * g2 + vv0[3] * g3;
        float u10 = vv1[0] * g0 + vv1[1] * g1, u11 = vv1[2] * g2 + vv1[3] * g3;
        #pragma unroll
        for (int j = 0; j < 4; j++) {
            float rc0 = u00 * sWr[j] + u01 * sWr[4 + j] + sbr[j] + q0[j];
            float rc1 = u10 * sWr[j] + u11 * sWr[4 + j] + sbr[j] + q1[j];
            u64 rc0p = pack2(rc0, rc0), rc1p = pack2(rc1, rc1);
            const float *wrow = sWo + (h * 4 + j) * 16;
            #pragma unroll
            for (int d2 = 0; d2 < 8; d2++) {
                u64 w = *(const u64 *)(wrow + d2 * 2);
                o0p[d2] = ffma2(rc0p, w, o0p[d2]);
                o1p[d2] = ffma2(rc1p, w, o1p[d2]);
            }
        }
    }
    #pragma unroll
    for (int j = 0; j < 8; j++) {
        float a, b2;
        unpack2(o0p[j], a, b2); x0[j * 2] += a; x0[j * 2 + 1] += b2;
        unpack2(o1p[j], a, b2); x1[j * 2] += a; x1[j * 2 + 1] += b2;
    }

    // FF block (LN2 folded into sWff1/sbff1), packed
    lnz_pack(x0, zp0); lnz_pack(x1, zp1);
    u64 a0p[8], a1p[8];
    #pragma unroll
    for (int j = 0; j < 8; j++) { a0p[j] = 0ull; a1p[j] = 0ull; }
    #pragma unroll
    for (int j4 = 0; j4 < 16; j4++) {
        u64 ta0 = *(const u64 *)(sbff1 + j4 * 4), tb0 = *(const u64 *)(sbff1 + j4 * 4 + 2);
        u64 ta1 = ta0, tb1 = tb0;
        #pragma unroll
        for (int d = 0; d < 16; d++) {
            ulonglong2 w = *(const ulonglong2 *)(sWff1 + d * 64 + j4 * 4);
            ta0 = ffma2(zp0[d], w.x, ta0); tb0 = ffma2(zp0[d], w.y, tb0);
            ta1 = ffma2(zp1[d], w.x, ta1); tb1 = ffma2(zp1[d], w.y, tb1);
        }
        float t0[4], t1[4];
        unpack2(ta0, t0[0], t0[1]); unpack2(tb0, t0[2], t0[3]);
        unpack2(ta1, t1[0], t1[1]); unpack2(tb1, t1[2], t1[3]);
        #pragma unroll
        for (int jj = 0; jj < 4; jj++) {
            float ga = gelu_exact(t0[jj]), gb = gelu_exact(t1[jj]);
            u64 gap = pack2(ga, ga), gbp = pack2(gb, gb);
            const float *w2 = sWff2 + (j4 * 4 + jj) * 16;
            #pragma unroll
            for (int d2 = 0; d2 < 8; d2++) {
                u64 w = *(const u64 *)(w2 + d2 * 2);
                a0p[d2] = ffma2(gap, w, a0p[d2]);
                a1p[d2] = ffma2(gbp, w, a1p[d2]);
            }
        }
    }
    #pragma unroll
    for (int j = 0; j < 8; j++) {
        float a, b2;
        unpack2(a0p[j], a, b2);
        x0[j * 2] += a + sbff2[j * 2]; x0[j * 2 + 1] += b2 + sbff2[j * 2 + 1];
        unpack2(a1p[j], a, b2);
        x1[j * 2] += a + sbff2[j * 2]; x1[j * 2 + 1] += b2 + sbff2[j * 2 + 1];
    }

    if (last) {
        float s0 = sbout, s1 = sbout;
        #pragma unroll
        for (int d = 0; d < 16; d++) { s0 = fmaf(x0[d], sWout[d], s0); s1 = fmaf(x1[d], sWout[d], s1); }
        if (v0 > 0.f) out[base + n0] = s0;
        if (v1 > 0.f) out[base + n1] = s1;
    } else {
        if (v0 > 0.f) store16s(base + n0, x0);
        if (v1 > 0.f) store16s(base + n1, x1);
        u64 zq0[16], zq1[16];
        lnz_pack(x0, zq0); lnz_pack(x1, zq1);
        float sS[NH], sW[NH][4];
        #pragma unroll
        for (int h = 0; h < NH; h++) { sS[h] = 0.f; sW[h][0] = sW[h][1] = sW[h][2] = sW[h][3] = 0.f; }
        passA2(zq0, zq1, rt0, rt1, v0, v1, sWqN, sbqN, swqlN, sS, sW);
        block_reduce_store(sS, sW, b, blockIdx.x, 0);
    }
}

// ---------------- launch ----------------
extern "C" void kernel_launch(void *const *d_in, const int *in_sizes, int n_in,
                              void *d_out, int out_size) {
    const float *corr  = (const float *)d_in[0];
    const float *Wemb  = (const float *)d_in[1];
    const float *bemb  = (const float *)d_in[2];
    const float *ln1g  = (const float *)d_in[3];
    const float *ln1b  = (const float *)d_in[4];
    const float *Wqkv  = (const float *)d_in[5];
    const float *wqlog = (const float *)d_in[6];
    const float *wklog = (const float *)d_in[7];
    const float *Wr    = (const float *)d_in[8];
    const float *br    = (const float *)d_in[9];
    const float *Wo    = (const float *)d_in[10];
    const float *bo    = (const float *)d_in[11];
    const float *ln2g  = (const float *)d_in[12];
    const float *ln2b  = (const float *)d_in[13];
    const float *Wff1  = (const float *)d_in[14];
    const float *bff1  = (const float *)d_in[15];
    const float *Wff2  = (const float *)d_in[16];
    const float *bff2  = (const float *)d_in[17];
    const float *Wout  = (const float *)d_in[18];
    const float *bout  = (const float *)d_in[19];
    float *out = (float *)d_out;
    (void)in_sizes; (void)n_in; (void)out_size;

    dim3 gridTok(NCH, NBATCH);
    k_prep<<<1, 256>>>(ln1g, ln1b, Wqkv, ln2g, ln2b, Wff1, bff1);
    k_rot<<<(NTOK + 255) / 256, 256>>>();
    k_embed<<<gridTok, TPB>>>(corr, Wemb, bemb, wqlog);
    for (int i = 0; i < LAYERS; i++) {
        k_passB<<<gridTok, TPB>>>(wklog, i);
        k_passC<<<gridTok, TPB>>>(Wr, br, Wo, bo, Wff2, bff2, wqlog, Wout, bout,
                                  out, i, i == LAYERS - 1 ? 1 : 0);
    }
}

// round 6
// speedup vs baseline: 8.3325x; 1.3365x over previous
#include <cuda_runtime.h>
#include <math.h>

#define LAYERS 6
#define DIM    16
#define NH     8
#define NBATCH 16
#define BOTD   26
#define NTOK   50625
#define TPB    256
#define UT     2                 // tokens per thread
#define SPAN   (TPB * UT)        // 512 tokens per block
#define NCH    99                // ceil(NTOK / SPAN)
#define LN_EPS 1e-5f

typedef unsigned long long u64;

// ---------------- static scratch ----------------
__device__ __align__(16) float4 g_x4[4][(size_t)NBATCH * NTOK];   // x planes (SoA)
__device__ __align__(16) float4 g_rot[NTOK];                      // c0,s0,c1,s1
// double-buffered softmax partials: buf0 = q-partials, buf1 = k-partials
__device__ float g_part[2][(size_t)NBATCH * NCH * 40];
// LN-folded weights
__device__ __align__(16) float c_Wqkv[LAYERS][DIM * 96];
__device__ __align__(16) float c_bqkv[LAYERS][96];
__device__ __align__(16) float c_Wff1[LAYERS][DIM * 64];
__device__ __align__(16) float c_bff1[LAYERS][64];
// attention-tail folds
__device__ __align__(16) float c_M1[LAYERS][256];   // Wq' @ Wo   [16x16]
__device__ __align__(16) float c_M2[LAYERS][256];   // Wr-blocks @ Wo [16x16]
__device__ __align__(16) float c_c0[LAYERS][16];    // bias terms @ Wo + bo
__device__ __align__(16) float c_w2o[64];           // Wff2 @ Wout (last layer)
__device__ float c_cout;                            // bff2 @ Wout + bout

// ---------------- f32x2 packed helpers ----------------
__device__ __forceinline__ u64 pack2(float x, float y) {
    u64 r; asm("mov.b64 %0, {%1, %2};" : "=l"(r) : "f"(x), "f"(y)); return r;
}
__device__ __forceinline__ void unpack2(u64 v, float &x, float &y) {
    asm("mov.b64 {%0, %1}, %2;" : "=f"(x), "=f"(y) : "l"(v));
}
__device__ __forceinline__ u64 ffma2(u64 a, u64 b, u64 c) {
    u64 r; asm("fma.rn.f32x2 %0, %1, %2, %3;" : "=l"(r) : "l"(a), "l"(b), "l"(c)); return r;
}

// ---------------- helpers ----------------
__device__ __forceinline__ void load16s(size_t idx, float x[16]) {
    #pragma unroll
    for (int p = 0; p < 4; p++) {
        float4 v = g_x4[p][idx];
        x[p * 4] = v.x; x[p * 4 + 1] = v.y; x[p * 4 + 2] = v.z; x[p * 4 + 3] = v.w;
    }
}
__device__ __forceinline__ void store16s(size_t idx, const float x[16]) {
    #pragma unroll
    for (int p = 0; p < 4; p++)
        g_x4[p][idx] = make_float4(x[p * 4], x[p * 4 + 1], x[p * 4 + 2], x[p * 4 + 3]);
}

// scalar LN (g/b folded downstream)
__device__ __forceinline__ void lnz(const float x[16], float z[16]) {
    float m = 0.f;
    #pragma unroll
    for (int d = 0; d < 16; d++) m += x[d];
    m *= 0.0625f;
    float v = 0.f;
    #pragma unroll
    for (int d = 0; d < 16; d++) { float t = x[d] - m; v = fmaf(t, t, v); }
    v *= 0.0625f;
    float inv = rsqrtf(v + LN_EPS);
    #pragma unroll
    for (int d = 0; d < 16; d++) z[d] = (x[d] - m) * inv;
}

// LN then broadcast-pack each lane
__device__ __forceinline__ void lnz_pack(const float x[16], u64 zp[16]) {
    float z[16];
    lnz(x, z);
    #pragma unroll
    for (int d = 0; d < 16; d++) zp[d] = pack2(z[d], z[d]);
}

// packed dual-token 16x4 dot: out = bias + z @ W[:, col..col+3]
__device__ __forceinline__ void dot2p(const u64 zp0[16], const u64 zp1[16],
                                      const float *W, const float *bias, int col,
                                      float k0[4], float k1[4]) {
    u64 a0 = *(const u64 *)(bias + col), b0 = *(const u64 *)(bias + col + 2);
    u64 a1 = a0, b1 = b0;
    #pragma unroll
    for (int d = 0; d < 16; d++) {
        ulonglong2 w = *(const ulonglong2 *)(W + d * 32 + col);
        a0 = ffma2(zp0[d], w.x, a0); b0 = ffma2(zp0[d], w.y, b0);
        a1 = ffma2(zp1[d], w.x, a1); b1 = ffma2(zp1[d], w.y, b1);
    }
    unpack2(a0, k0[0], k0[1]); unpack2(b0, k0[2], k0[3]);
    unpack2(a1, k1[0], k1[1]); unpack2(b1, k1[2], k1[3]);
}

__device__ __forceinline__ float gelu_exact(float t) {
    float xx = t * 0.70710678118654752440f;
    float a  = fabsf(xx);
    float u  = __fdividef(1.f, fmaf(0.3275911f, a, 1.f));
    float p  = u * (0.254829592f + u * (-0.284496736f + u * (1.421413741f +
               u * (-1.453152027f + u * 1.061405429f))));
    float er = 1.f - p * __expf(-a * a);
    er = copysignf(er, xx);
    return 0.5f * t * (1.f + er);
}

__device__ __forceinline__ void sm_acc(float &s, float w[4], float l, float vmask,
                                       float a0, float a1, float a2, float a3) {
    float p = __expf(l) * vmask;
    s += p;
    w[0] = fmaf(p, a0, w[0]); w[1] = fmaf(p, a1, w[1]);
    w[2] = fmaf(p, a2, w[2]); w[3] = fmaf(p, a3, w[3]);
}

__device__ __forceinline__ void block_reduce_store(float sS[NH], float sW[NH][4],
                                                   int b, int chunk, int buf) {
    const unsigned FULL = 0xffffffffu;
    #pragma unroll
    for (int off = 16; off; off >>= 1) {
        #pragma unroll
        for (int h = 0; h < NH; h++) {
            sS[h]    += __shfl_xor_sync(FULL, sS[h],    off);
            sW[h][0] += __shfl_xor_sync(FULL, sW[h][0], off);
            sW[h][1] += __shfl_xor_sync(FULL, sW[h][1], off);
            sW[h][2] += __shfl_xor_sync(FULL, sW[h][2], off);
            sW[h][3] += __shfl_xor_sync(FULL, sW[h][3], off);
        }
    }
    __shared__ float sred[TPB / 32][40];
    int wid = threadIdx.x >> 5, lane = threadIdx.x & 31;
    if (lane == 0) {
        #pragma unroll
        for (int h = 0; h < NH; h++) {
            sred[wid][h * 5 + 0] = sS[h];
            sred[wid][h * 5 + 1] = sW[h][0]; sred[wid][h * 5 + 2] = sW[h][1];
            sred[wid][h * 5 + 3] = sW[h][2]; sred[wid][h * 5 + 4] = sW[h][3];
        }
    }
    __syncthreads();
    if (threadIdx.x < 40) {
        float acc = 0.f;
        #pragma unroll
        for (int w = 0; w < TPB / 32; w++) acc += sred[w][threadIdx.x];
        g_part[buf][(size_t)(b * NCH + chunk) * 40 + threadIdx.x] = acc;
    }
}

// prologue: reduce this batch's partials (buf) into normalized global vector sg[32]
__device__ __forceinline__ void reduce_global(int b, int buf, float sg[32]) {
    __shared__ float spart[6][40];
    int tid = threadIdx.x;
    if (tid < 240) {
        int sub = tid / 40, f = tid % 40;
        float s = 0.f;
        for (int c = sub; c < NCH; c += 6)
            s += g_part[buf][(size_t)(b * NCH + c) * 40 + f];
        spart[sub][f] = s;
    }
    __syncthreads();
    if (tid < 8) {
        float s = 0.f;
        #pragma unroll
        for (int k = 0; k < 6; k++) s += spart[k][tid * 5];
        float inv = 1.f / s;
        #pragma unroll
        for (int j = 0; j < 4; j++) {
            float w = 0.f;
            #pragma unroll
            for (int k = 0; k < 6; k++) w += spart[k][tid * 5 + 1 + j];
            sg[tid * 4 + j] = w * inv;
        }
    }
    __syncthreads();
}

// pass-A contribution of two tokens (q logits + rotary aggr), packed math
__device__ __forceinline__ void passA2(const u64 zp0[16], const u64 zp1[16],
                                       float4 rt0, float4 rt1, float v0, float v1,
                                       const float *Wq, const float *bq, const float *wql,
                                       float sS[NH], float sW[NH][4]) {
    #pragma unroll
    for (int h = 0; h < NH; h++) {
        float q0[4], q1[4];
        dot2p(zp0, zp1, Wq, bq, h * 4, q0, q1);
        float l0 = (q0[0] * wql[0] + q0[1] * wql[1] + q0[2] * wql[2] + q0[3] * wql[3]) * 0.5f;
        float l1 = (q1[0] * wql[0] + q1[1] * wql[1] + q1[2] * wql[2] + q1[3] * wql[3]) * 0.5f;
        sm_acc(sS[h], sW[h], l0, v0,
               q0[0] * rt0.x - q0[1] * rt0.y, q0[1] * rt0.x + q0[0] * rt0.y,
               q0[2] * rt0.z - q0[3] * rt0.w, q0[3] * rt0.z + q0[2] * rt0.w);
        sm_acc(sS[h], sW[h], l1, v1,
               q1[0] * rt1.x - q1[1] * rt1.y, q1[1] * rt1.x + q1[0] * rt1.y,
               q1[2] * rt1.z - q1[3] * rt1.w, q1[3] * rt1.z + q1[2] * rt1.w);
    }
}

// ---------------- kernels ----------------
__global__ void k_rot() {
    int n = blockIdx.x * blockDim.x + threadIdx.x;
    if (n >= NTOK) return;
    float t = (float)n;
    float s0, c0, s1, c1;
    sincosf(t * (float)M_PI, &s0, &c0);
    sincosf(t * (float)(5.0 * M_PI), &s1, &c1);
    g_rot[n] = make_float4(c0, s0, c1, s1);
}

// fold LN g/b into weights; precompute attention-tail matrices M1/M2/c0 and last-layer Wout folds
__global__ void k_prep(const float *__restrict__ ln1g, const float *__restrict__ ln1b,
                       const float *__restrict__ Wqkv,
                       const float *__restrict__ ln2g, const float *__restrict__ ln2b,
                       const float *__restrict__ Wff1, const float *__restrict__ bff1,
                       const float *__restrict__ Wr, const float *__restrict__ br,
                       const float *__restrict__ Wo, const float *__restrict__ bo,
                       const float *__restrict__ Wff2, const float *__restrict__ bff2,
                       const float *__restrict__ Wout, const float *__restrict__ bout) {
    int tid = threadIdx.x;
    for (int i = tid; i < LAYERS * DIM * 96; i += blockDim.x) {
        int l = i / (DIM * 96), r = i % (DIM * 96), d = r / 96;
        c_Wqkv[l][r] = ln1g[l * 16 + d] * Wqkv[i];
    }
    for (int i = tid; i < LAYERS * 96; i += blockDim.x) {
        int l = i / 96, c = i % 96;
        float s = 0.f;
        for (int d = 0; d < 16; d++) s += ln1b[l * 16 + d] * Wqkv[(l * 16 + d) * 96 + c];
        c_bqkv[l][c] = s;
    }
    for (int i = tid; i < LAYERS * DIM * 64; i += blockDim.x) {
        int l = i / (DIM * 64), r = i % (DIM * 64), d = r / 64;
        c_Wff1[l][r] = ln2g[l * 16 + d] * Wff1[i];
    }
    for (int i = tid; i < LAYERS * 64; i += blockDim.x) {
        int l = i / 64, c = i % 64;
        float s = bff1[i];
        for (int d = 0; d < 16; d++) s += ln2b[l * 16 + d] * Wff1[(l * 16 + d) * 64 + c];
        c_bff1[l][c] = s;
    }
    __syncthreads();
    // M1 = Wq'(folded) @ Wo ; M2 = per-head Wr @ Wo
    for (int i = tid; i < LAYERS * 256; i += blockDim.x) {
        int l = i >> 8, r = i & 255, d = r >> 4, e = r & 15;
        float s = 0.f;
        for (int c = 0; c < 32; c++) s += c_Wqkv[l][d * 96 + c] * Wo[l * 512 + c * 16 + e];
        c_M1[l][r] = s;
        int h = d >> 1, ii = d & 1;     // reuse r-index as (m,e), m=d
        float s2 = 0.f;
        for (int j = 0; j < 4; j++) s2 += Wr[l * 8 + ii * 4 + j] * Wo[l * 512 + (h * 4 + j) * 16 + e];
        c_M2[l][r] = s2;
    }
    // c0 = bq'@Wo + (br per head)@Wo + bo
    for (int i = tid; i < LAYERS * 16; i += blockDim.x) {
        int l = i >> 4, e = i & 15;
        float s = bo[l * 16 + e];
        for (int c = 0; c < 32; c++) s += c_bqkv[l][c] * Wo[l * 512 + c * 16 + e];
        for (int h = 0; h < NH; h++)
            for (int j = 0; j < 4; j++) s += br[l * 4 + j] * Wo[l * 512 + (h * 4 + j) * 16 + e];
        c_c0[l][e] = s;
    }
    // last layer: fold Wff2 through Wout
    for (int i = tid; i < 64; i += blockDim.x) {
        float s = 0.f;
        for (int e = 0; e < 16; e++) s += Wff2[(LAYERS - 1) * 1024 + i * 16 + e] * Wout[e];
        c_w2o[i] = s;
    }
    if (tid == 0) {
        float s = bout[0];
        for (int e = 0; e < 16; e++) s += bff2[(LAYERS - 1) * 16 + e] * Wout[e];
        c_cout = s;
    }
}

// embedding + fused pass-A of layer 0 (writes q-partials into buf 0)
__global__ void __launch_bounds__(TPB, 2) k_embed(
    const float *__restrict__ corr, const float *__restrict__ Wemb, const float *__restrict__ bemb,
    const float *__restrict__ wqlog) {
    __shared__ __align__(16) float sWemb[BOTD * DIM];
    __shared__ __align__(16) float sbemb[DIM], sbq[32];
    __shared__ float swql[4];
    __shared__ __align__(16) float sWq[DIM * 32];
    int tid = threadIdx.x, b = blockIdx.y;
    for (int i = tid; i < BOTD * DIM; i += TPB) sWemb[i] = Wemb[i];
    for (int i = tid; i < DIM; i += TPB) sbemb[i] = bemb[i];
    for (int i = tid; i < DIM * 32; i += TPB) { int d = i >> 5, c = i & 31; sWq[i] = c_Wqkv[0][d * 96 + c]; }
    for (int i = tid; i < 32; i += TPB) sbq[i] = c_bqkv[0][i];
    if (tid < 4) swql[tid] = wqlog[tid];
    __syncthreads();

    int n0 = blockIdx.x * SPAN + tid, n1 = n0 + TPB;
    float v0 = n0 < NTOK ? 1.f : 0.f, v1 = n1 < NTOK ? 1.f : 0.f;
    const float *cb = corr + (size_t)b * BOTD * NTOK;

    u64 x0p[8], x1p[8];
    #pragma unroll
    for (int j = 0; j < 8; j++) { x0p[j] = *(const u64 *)(sbemb + j * 2); x1p[j] = x0p[j]; }
    #pragma unroll 2
    for (int c = 0; c < BOTD; c++) {
        float c0 = v0 > 0.f ? fmaxf(cb[c * NTOK + n0], 0.f) : 0.f;
        float c1 = v1 > 0.f ? fmaxf(cb[c * NTOK + n1], 0.f) : 0.f;
        u64 c0p = pack2(c0, c0), c1p = pack2(c1, c1);
        #pragma unroll
        for (int j4 = 0; j4 < 4; j4++) {
            ulonglong2 w = *(const ulonglong2 *)(sWemb + c * 16 + j4 * 4);
            x0p[j4 * 2]     = ffma2(c0p, w.x, x0p[j4 * 2]);
            x0p[j4 * 2 + 1] = ffma2(c0p, w.y, x0p[j4 * 2 + 1]);
            x1p[j4 * 2]     = ffma2(c1p, w.x, x1p[j4 * 2]);
            x1p[j4 * 2 + 1] = ffma2(c1p, w.y, x1p[j4 * 2 + 1]);
        }
    }
    float x0[16], x1[16];
    #pragma unroll
    for (int j = 0; j < 8; j++) {
        unpack2(x0p[j], x0[j * 2], x0[j * 2 + 1]);
        unpack2(x1p[j], x1[j * 2], x1[j * 2 + 1]);
    }
    if (v0 > 0.f) store16s((size_t)b * NTOK + n0, x0);
    if (v1 > 0.f) store16s((size_t)b * NTOK + n1, x1);
    float4 rt0 = v0 > 0.f ? g_rot[n0] : make_float4(1, 0, 1, 0);
    float4 rt1 = v1 > 0.f ? g_rot[n1] : make_float4(1, 0, 1, 0);

    u64 zp0[16], zp1[16];
    lnz_pack(x0, zp0); lnz_pack(x1, zp1);
    float sS[NH], sW[NH][4];
    #pragma unroll
    for (int h = 0; h < NH; h++) { sS[h] = 0.f; sW[h][0] = sW[h][1] = sW[h][2] = sW[h][3] = 0.f; }
    passA2(zp0, zp1, rt0, rt1, v0, v1, sWq, sbq, swql, sS, sW);
    block_reduce_store(sS, sW, b, blockIdx.x, 0);
}

// pass-B: reduce q-partials (buf0) -> global_q; k logits -> k-partials (buf1)
__global__ void __launch_bounds__(TPB, 2) k_passB(
    const float *__restrict__ wklog_all, int layer) {
    __shared__ float swkl[2], sgq[32];
    __shared__ __align__(16) float sbk[32];
    __shared__ __align__(16) float sWk[DIM * 32];
    int tid = threadIdx.x, b = blockIdx.y;
    for (int i = tid; i < 512; i += TPB) { int d = i >> 5, c = i & 31; sWk[i] = c_Wqkv[layer][d * 96 + 32 + c]; }
    for (int i = tid; i < 32; i += TPB) sbk[i] = c_bqkv[layer][32 + i];
    if (tid < 2) swkl[tid] = wklog_all[layer * 2 + tid];
    reduce_global(b, 0, sgq);

    int n0 = blockIdx.x * SPAN + tid, n1 = n0 + TPB;
    float v0 = n0 < NTOK ? 1.f : 0.f, v1 = n1 < NTOK ? 1.f : 0.f;
    size_t base = (size_t)b * NTOK;
    float x0[16] = {0.f}, x1[16] = {0.f};
    if (v0 > 0.f) load16s(base + n0, x0);
    if (v1 > 0.f) load16s(base + n1, x1);
    float4 rt0 = v0 > 0.f ? g_rot[n0] : make_float4(1, 0, 1, 0);
    float4 rt1 = v1 > 0.f ? g_rot[n1] : make_float4(1, 0, 1, 0);

    u64 zp0[16], zp1[16];
    lnz_pack(x0, zp0); lnz_pack(x1, zp1);

    float sS[NH], sW[NH][4];
    #pragma unroll
    for (int h = 0; h < NH; h++) { sS[h] = 0.f; sW[h][0] = sW[h][1] = sW[h][2] = sW[h][3] = 0.f; }

    #pragma unroll
    for (int h = 0; h < NH; h++) {
        float k0[4], k1[4];
        dot2p(zp0, zp1, sWk, sbk, h * 4, k0, k1);
        float g0 = sgq[h * 4 + 0], g1 = sgq[h * 4 + 1], g2 = sgq[h * 4 + 2], g3 = sgq[h * 4 + 3];
        float l0 = ((k0[0] * g0 + k0[1] * g1) * swkl[0] + (k0[2] * g2 + k0[3] * g3) * swkl[1]) * 0.5f;
        float l1 = ((k1[0] * g0 + k1[1] * g1) * swkl[0] + (k1[2] * g2 + k1[3] * g3) * swkl[1]) * 0.5f;
        sm_acc(sS[h], sW[h], l0, v0,
               k0[0] * rt0.x - k0[1] * rt0.y, k0[1] * rt0.x + k0[0] * rt0.y,
               k0[2] * rt0.z - k0[3] * rt0.w, k0[3] * rt0.z + k0[2] * rt0.w);
        sm_acc(sS[h], sW[h], l1, v1,
               k1[0] * rt1.x - k1[1] * rt1.y, k1[1] * rt1.x + k1[0] * rt1.y,
               k1[2] * rt1.z - k1[3] * rt1.w, k1[3] * rt1.z + k1[2] * rt1.w);
    }
    block_reduce_store(sS, sW, b, blockIdx.x, 1);
}

// pass-C v3: folded attention tail (z@M + c) -> residual -> FF -> residual, + next pass-A
__global__ void __launch_bounds__(TPB, 2) k_passC(
    const float *__restrict__ Wff2_all, const float *__restrict__ bff2_all,
    const float *__restrict__ wqlog_all, const float *__restrict__ Wout,
    float *__restrict__ out, int layer, int last) {
    __shared__ float sgk[32], swqlN[4], sWout[16], scout;
    __shared__ __align__(16) float sWu[256], sM[256], sc[16];
    __shared__ __align__(16) float sbff1[64], sbff2[16], sbqN[32], sw2o[64];
    __shared__ __align__(16) float sWff1[1024], sWff2[1024], sWqN[512];
    int tid = threadIdx.x, b = blockIdx.y;

    for (int i = tid; i < 1024; i += TPB) sWff1[i] = c_Wff1[layer][i];
    for (int i = tid; i < 64; i += TPB) sbff1[i] = c_bff1[layer][i];
    if (!last) {
        int nl = layer + 1;
        for (int i = tid; i < 1024; i += TPB) sWff2[i] = Wff2_all[layer * 1024 + i];
        for (int i = tid; i < 16; i += TPB) sbff2[i] = bff2_all[layer * 16 + i];
        for (int i = tid; i < 512; i += TPB) { int d = i >> 5, c = i & 31; sWqN[i] = c_Wqkv[nl][d * 96 + c]; }
        for (int i = tid; i < 32; i += TPB) sbqN[i] = c_bqkv[nl][i];
        if (tid < 4) swqlN[tid] = wqlog_all[nl * 4 + tid];
    } else {
        for (int i = tid; i < 64; i += TPB) sw2o[i] = c_w2o[i];
        for (int i = tid; i < 16; i += TPB) sWout[i] = Wout[i];
        if (tid == 0) scout = c_cout;
    }
    reduce_global(b, 1, sgk);

    // fold gk into the v->u->r->Wo path: M = M1 + (Wv' .gk-pairsum) @ M2, c = c0 + bu @ M2
    {
        int d = tid >> 4, m = tid & 15;
        const float *wv = &c_Wqkv[layer][d * 96 + 64];
        sWu[tid] = wv[2 * m] * sgk[2 * m] + wv[2 * m + 1] * sgk[2 * m + 1];
    }
    __syncthreads();
    {
        int d = tid >> 4, e = tid & 15;
        float acc = c_M1[layer][tid];
        #pragma unroll 4
        for (int m = 0; m < 16; m++) acc = fmaf(sWu[d * 16 + m], c_M2[layer][m * 16 + e], acc);
        sM[tid] = acc;
    }
    if (tid < 16) {
        float acc = c_c0[layer][tid];
        #pragma unroll 4
        for (int m = 0; m < 16; m++) {
            float bu = c_bqkv[layer][64 + 2 * m] * sgk[2 * m] + c_bqkv[layer][64 + 2 * m + 1] * sgk[2 * m + 1];
            acc = fmaf(bu, c_M2[layer][m * 16 + tid], acc);
        }
        sc[tid] = acc;
    }
    __syncthreads();

    int n0 = blockIdx.x * SPAN + tid, n1 = n0 + TPB;
    float v0 = n0 < NTOK ? 1.f : 0.f, v1 = n1 < NTOK ? 1.f : 0.f;
    size_t base = (size_t)b * NTOK;
    float x0[16] = {0.f}, x1[16] = {0.f};
    if (v0 > 0.f) load16s(base + n0, x0);
    if (v1 > 0.f) load16s(base + n1, x1);

    // attention tail: x += z @ M + c  (entire q/v/u/r/Wo path folded)
    {
        float z0[16], z1[16];
        lnz(x0, z0); lnz(x1, z1);
        float d0[16], d1[16];
        #pragma unroll
        for (int e = 0; e < 16; e++) { d0[e] = sc[e]; d1[e] = sc[e]; }
        #pragma unroll
        for (int d = 0; d < 16; d++) {
            float za = z0[d], zb = z1[d];
            #pragma unroll
            for (int e4 = 0; e4 < 4; e4++) {
                float4 w = *(const float4 *)(sM + d * 16 + e4 * 4);
                d0[e4 * 4 + 0] = fmaf(za, w.x, d0[e4 * 4 + 0]);
                d0[e4 * 4 + 1] = fmaf(za, w.y, d0[e4 * 4 + 1]);
                d0[e4 * 4 + 2] = fmaf(za, w.z, d0[e4 * 4 + 2]);
                d0[e4 * 4 + 3] = fmaf(za, w.w, d0[e4 * 4 + 3]);
                d1[e4 * 4 + 0] = fmaf(zb, w.x, d1[e4 * 4 + 0]);
                d1[e4 * 4 + 1] = fmaf(zb, w.y, d1[e4 * 4 + 1]);
                d1[e4 * 4 + 2] = fmaf(zb, w.z, d1[e4 * 4 + 2]);
                d1[e4 * 4 + 3] = fmaf(zb, w.w, d1[e4 * 4 + 3]);
            }
        }
        #pragma unroll
        for (int e = 0; e < 16; e++) { x0[e] += d0[e]; x1[e] += d1[e]; }
    }

    // FF block (LN2 folded into sWff1/sbff1)
    u64 zp0[16], zp1[16];
    lnz_pack(x0, zp0); lnz_pack(x1, zp1);

    if (!last) {
        u64 a0p[8], a1p[8];
        #pragma unroll
        for (int j = 0; j < 8; j++) { a0p[j] = 0ull; a1p[j] = 0ull; }
        #pragma unroll
        for (int j4 = 0; j4 < 16; j4++) {
            u64 ta0 = *(const u64 *)(sbff1 + j4 * 4), tb0 = *(const u64 *)(sbff1 + j4 * 4 + 2);
            u64 ta1 = ta0, tb1 = tb0;
            #pragma unroll
            for (int d = 0; d < 16; d++) {
                ulonglong2 w = *(const ulonglong2 *)(sWff1 + d * 64 + j4 * 4);
                ta0 = ffma2(zp0[d], w.x, ta0); tb0 = ffma2(zp0[d], w.y, tb0);
                ta1 = ffma2(zp1[d], w.x, ta1); tb1 = ffma2(zp1[d], w.y, tb1);
            }
            float t0[4], t1[4];
            unpack2(ta0, t0[0], t0[1]); unpack2(tb0, t0[2], t0[3]);
            unpack2(ta1, t1[0], t1[1]); unpack2(tb1, t1[2], t1[3]);
            #pragma unroll
            for (int jj = 0; jj < 4; jj++) {
                float ga = gelu_exact(t0[jj]), gb = gelu_exact(t1[jj]);
                u64 gap = pack2(ga, ga), gbp = pack2(gb, gb);
                const float *w2 = sWff2 + (j4 * 4 + jj) * 16;
                #pragma unroll
                for (int d2 = 0; d2 < 8; d2++) {
                    u64 w = *(const u64 *)(w2 + d2 * 2);
                    a0p[d2] = ffma2(gap, w, a0p[d2]);
                    a1p[d2] = ffma2(gbp, w, a1p[d2]);
                }
            }
        }
        #pragma unroll
        for (int j = 0; j < 8; j++) {
            float a, b2;
            unpack2(a0p[j], a, b2);
            x0[j * 2] += a + sbff2[j * 2]; x0[j * 2 + 1] += b2 + sbff2[j * 2 + 1];
            unpack2(a1p[j], a, b2);
            x1[j * 2] += a + sbff2[j * 2]; x1[j * 2 + 1] += b2 + sbff2[j * 2 + 1];
        }
        if (v0 > 0.f) store16s(base + n0, x0);
        if (v1 > 0.f) store16s(base + n1, x1);
        float4 rt0 = v0 > 0.f ? g_rot[n0] : make_float4(1, 0, 1, 0);
        float4 rt1 = v1 > 0.f ? g_rot[n1] : make_float4(1, 0, 1, 0);
        u64 zq0[16], zq1[16];
        lnz_pack(x0, zq0); lnz_pack(x1, zq1);
        float sS[NH], sW[NH][4];
        #pragma unroll
        for (int h = 0; h < NH; h++) { sS[h] = 0.f; sW[h][0] = sW[h][1] = sW[h][2] = sW[h][3] = 0.f; }
        passA2(zq0, zq1, rt0, rt1, v0, v1, sWqN, sbqN, swqlN, sS, sW);
        block_reduce_store(sS, sW, b, blockIdx.x, 0);
    } else {
        // last layer: out = x_attn@Wout + gelu(ff1)@(Wff2@Wout) + const
        float og0 = scout, og1 = scout;
        #pragma unroll
        for (int j4 = 0; j4 < 16; j4++) {
            u64 ta0 = *(const u64 *)(sbff1 + j4 * 4), tb0 = *(const u64 *)(sbff1 + j4 * 4 + 2);
            u64 ta1 = ta0, tb1 = tb0;
            #pragma unroll
            for (int d = 0; d < 16; d++) {
                ulonglong2 w = *(const ulonglong2 *)(sWff1 + d * 64 + j4 * 4);
                ta0 = ffma2(zp0[d], w.x, ta0); tb0 = ffma2(zp0[d], w.y, tb0);
                ta1 = ffma2(zp1[d], w.x, ta1); tb1 = ffma2(zp1[d], w.y, tb1);
            }
            float t0[4], t1[4];
            unpack2(ta0, t0[0], t0[1]); unpack2(tb0, t0[2], t0[3]);
            unpack2(ta1, t1[0], t1[1]); unpack2(tb1, t1[2], t1[3]);
            #pragma unroll
            for (int jj = 0; jj < 4; jj++) {
                float wj = sw2o[j4 * 4 + jj];
                og0 = fmaf(gelu_exact(t0[jj]), wj, og0);
                og1 = fmaf(gelu_exact(t1[jj]), wj, og1);
            }
        }
        #pragma unroll
        for (int d = 0; d < 16; d++) {
            float wd = sWout[d];
            og0 = fmaf(x0[d], wd, og0);
            og1 = fmaf(x1[d], wd, og1);
        }
        if (v0 > 0.f) out[base + n0] = og0;
        if (v1 > 0.f) out[base + n1] = og1;
    }
}

// ---------------- launch ----------------
extern "C" void kernel_launch(void *const *d_in, const int *in_sizes, int n_in,
                              void *d_out, int out_size) {
    const float *corr  = (const float *)d_in[0];
    const float *Wemb  = (const float *)d_in[1];
    const float *bemb  = (const float *)d_in[2];
    const float *ln1g  = (const float *)d_in[3];
    const float *ln1b  = (const float *)d_in[4];
    const float *Wqkv  = (const float *)d_in[5];
    const float *wqlog = (const float *)d_in[6];
    const float *wklog = (const float *)d_in[7];
    const float *Wr    = (const float *)d_in[8];
    const float *br    = (const float *)d_in[9];
    const float *Wo    = (const float *)d_in[10];
    const float *bo    = (const float *)d_in[11];
    const float *ln2g  = (const float *)d_in[12];
    const float *ln2b  = (const float *)d_in[13];
    const float *Wff1  = (const float *)d_in[14];
    const float *bff1  = (const float *)d_in[15];
    const float *Wff2  = (const float *)d_in[16];
    const float *bff2  = (const float *)d_in[17];
    const float *Wout  = (const float *)d_in[18];
    const float *bout  = (const float *)d_in[19];
    float *out = (float *)d_out;
    (void)in_sizes; (void)n_in; (void)out_size;

    dim3 gridTok(NCH, NBATCH);
    k_prep<<<1, 256>>>(ln1g, ln1b, Wqkv, ln2g, ln2b, Wff1, bff1,
                       Wr, br, Wo, bo, Wff2, bff2, Wout, bout);
    k_rot<<<(NTOK + 255) / 256, 256>>>();
    k_embed<<<gridTok, TPB>>>(corr, Wemb, bemb, wqlog);
    for (int i = 0; i < LAYERS; i++) {
        k_passB<<<gridTok, TPB>>>(wklog, i);
        k_passC<<<gridTok, TPB>>>(Wff2, bff2, wqlog, Wout,
                                  out, i, i == LAYERS - 1 ? 1 : 0);
    }
}